// round 3
// baseline (speedup 1.0000x reference)
#include <cuda_runtime.h>
#include <math.h>
#include <stdint.h>

#define BATCH 2
#define LQ 13294
#define LEN_IN 13294
#define DM 256
#define NH 8
#define HD 32
#define MROWS (BATCH * LQ)   // 26588

// ---------------- scratch (device globals; no allocations allowed) ----------
__device__ float g_value[(size_t)BATCH * LEN_IN * DM];   // [B, LEN_IN, NH, HD]
__device__ float g_offs[(size_t)BATCH * LQ * DM];        // [B, LQ, NH, 16, 2]
__device__ float g_logits[(size_t)BATCH * LQ * NH * 16]; // [B, LQ, NH, 16]
__device__ float g_acc[(size_t)BATCH * LQ * DM];         // [B, LQ, NH, HD]

// ---------------- helpers ---------------------------------------------------
__device__ __forceinline__ unsigned f2tf(float x) {
    unsigned r;
    asm("cvt.rna.tf32.f32 %0, %1;" : "=r"(r) : "f"(x));
    return r;
}

__device__ __forceinline__ void mma_tf32(float* d,
    unsigned a0, unsigned a1, unsigned a2, unsigned a3,
    unsigned b0, unsigned b1)
{
    asm volatile(
        "mma.sync.aligned.m16n8k8.row.col.f32.tf32.tf32.f32 "
        "{%0,%1,%2,%3}, {%4,%5,%6,%7}, {%8,%9}, {%0,%1,%2,%3};"
        : "+f"(d[0]), "+f"(d[1]), "+f"(d[2]), "+f"(d[3])
        : "r"(a0), "r"(a1), "r"(a2), "r"(a3), "r"(b0), "r"(b1));
}

// ---------------- tensor-core GEMM (3xTF32): C = A@B + bias -----------------
// BM=128, BN=128, BK=16, 256 threads (8 warps: 2 M x 4 N), warp tile 64x32.
// SMEM fragment-packed layout: per row, per s(k8-step), per tg: float4
//   { hi(k=s*8+tg), hi(k=s*8+tg+4), lo(k=s*8+tg), lo(k=s*8+tg+4) }
#define RSTRIDE 36   // floats per row: 32 payload + 4 pad (bank spread)

__global__ __launch_bounds__(256) void mma_gemm_kernel(
    const float* __restrict__ A, const float* __restrict__ B,
    const float* __restrict__ bias, float* __restrict__ C,
    int M, int N, int K)
{
    __shared__ __align__(16) float As[128 * RSTRIDE];
    __shared__ __align__(16) float Bs[128 * RSTRIDE];

    const int tid = threadIdx.x;
    const int lane = tid & 31;
    const int wid = tid >> 5;
    const int warp_m = wid & 1;   // 0..1  -> 64 rows each
    const int warp_n = wid >> 1;  // 0..3  -> 32 cols each
    const int g  = lane >> 2;     // groupID
    const int tg = lane & 3;      // threadID_in_group
    const int bm = blockIdx.y * 128;
    const int bn = blockIdx.x * 128;

    // gmem loaders (same tiling as fp32 version)
    const int arow  = tid >> 2;        // 0..63 (+64)
    const int acol4 = (tid & 3) * 4;   // 0,4,8,12 (same s and j for all 4 elems)
    const int a_s = acol4 >> 3;
    const int a_j = (acol4 >> 2) & 1;
    const int brow = tid >> 5;         // 0..7 (+8)
    const int bcol = (tid & 31) * 4;

    const int nch = K / 16;
    float4 pa[2], pb[2];

    // prefetch chunk 0
    #pragma unroll
    for (int r = 0; r < 2; ++r) {
        const int row = bm + arow + r * 64;
        pa[r] = make_float4(0.f, 0.f, 0.f, 0.f);
        if (row < M)
            pa[r] = *reinterpret_cast<const float4*>(A + (size_t)row * K + acol4);
        pb[r] = *reinterpret_cast<const float4*>(B + (size_t)(brow + r * 8) * N + bn + bcol);
    }

    float acc[4][4][4];
    #pragma unroll
    for (int i = 0; i < 4; ++i)
        #pragma unroll
        for (int j = 0; j < 4; ++j)
            #pragma unroll
            for (int e = 0; e < 4; ++e) acc[i][j][e] = 0.f;

    for (int c = 0; c < nch; ++c) {
        // ---- convert + store prefetched regs into smem fragment layout ----
        #pragma unroll
        for (int r = 0; r < 2; ++r) {
            // A: row = arow + r*64, k = acol4 + e  (tg = e)
            float* ap = As + (arow + r * 64) * RSTRIDE + a_s * 16;
            const float va[4] = {pa[r].x, pa[r].y, pa[r].z, pa[r].w};
            #pragma unroll
            for (int e = 0; e < 4; ++e) {
                const unsigned hi = f2tf(va[e]);
                const unsigned lo = f2tf(va[e] - __uint_as_float(hi));
                ap[e * 4 + a_j]     = __uint_as_float(hi);
                ap[e * 4 + 2 + a_j] = __uint_as_float(lo);
            }
            // B: k = brow + r*8 (fixed s,j,tg), col = bcol + e
            const int bk = brow + r * 8;
            const int b_s = bk >> 3, b_j = (bk >> 2) & 1, b_tg = bk & 3;
            const float vbv[4] = {pb[r].x, pb[r].y, pb[r].z, pb[r].w};
            #pragma unroll
            for (int e = 0; e < 4; ++e) {
                const unsigned hi = f2tf(vbv[e]);
                const unsigned lo = f2tf(vbv[e] - __uint_as_float(hi));
                float* bp = Bs + (bcol + e) * RSTRIDE + b_s * 16 + b_tg * 4;
                bp[b_j]     = __uint_as_float(hi);
                bp[2 + b_j] = __uint_as_float(lo);
            }
        }
        __syncthreads();

        // ---- prefetch next chunk ----
        if (c + 1 < nch) {
            const int k0 = (c + 1) * 16;
            #pragma unroll
            for (int r = 0; r < 2; ++r) {
                const int row = bm + arow + r * 64;
                pa[r] = make_float4(0.f, 0.f, 0.f, 0.f);
                if (row < M)
                    pa[r] = *reinterpret_cast<const float4*>(A + (size_t)row * K + k0 + acol4);
                pb[r] = *reinterpret_cast<const float4*>(B + (size_t)(k0 + brow + r * 8) * N + bn + bcol);
            }
        }

        // ---- compute: 2 k8 steps, 4x4 mma tiles, 3x split ----
        #pragma unroll
        for (int s = 0; s < 2; ++s) {
            float4 apk[4][2];
            #pragma unroll
            for (int mi = 0; mi < 4; ++mi)
                #pragma unroll
                for (int ro = 0; ro < 2; ++ro)
                    apk[mi][ro] = *reinterpret_cast<const float4*>(
                        As + (warp_m * 64 + mi * 16 + g + ro * 8) * RSTRIDE + s * 16 + tg * 4);

            #pragma unroll
            for (int ni = 0; ni < 4; ++ni) {
                const float4 bpk = *reinterpret_cast<const float4*>(
                    Bs + (warp_n * 32 + ni * 8 + g) * RSTRIDE + s * 16 + tg * 4);
                const unsigned bh0 = __float_as_uint(bpk.x);
                const unsigned bh1 = __float_as_uint(bpk.y);
                const unsigned bl0 = __float_as_uint(bpk.z);
                const unsigned bl1 = __float_as_uint(bpk.w);
                #pragma unroll
                for (int mi = 0; mi < 4; ++mi) {
                    const unsigned ah0 = __float_as_uint(apk[mi][0].x); // (g,    tg)
                    const unsigned ah1 = __float_as_uint(apk[mi][1].x); // (g+8,  tg)
                    const unsigned ah2 = __float_as_uint(apk[mi][0].y); // (g,    tg+4)
                    const unsigned ah3 = __float_as_uint(apk[mi][1].y); // (g+8,  tg+4)
                    const unsigned al0 = __float_as_uint(apk[mi][0].z);
                    const unsigned al1 = __float_as_uint(apk[mi][1].z);
                    const unsigned al2 = __float_as_uint(apk[mi][0].w);
                    const unsigned al3 = __float_as_uint(apk[mi][1].w);
                    mma_tf32(acc[mi][ni], ah0, ah1, ah2, ah3, bh0, bh1);
                    mma_tf32(acc[mi][ni], ah0, ah1, ah2, ah3, bl0, bl1);
                    mma_tf32(acc[mi][ni], al0, al1, al2, al3, bh0, bh1);
                }
            }
        }
        __syncthreads();
    }

    // ---- epilogue: D + bias, float2 stores ----
    #pragma unroll
    for (int mi = 0; mi < 4; ++mi) {
        const int row0 = bm + warp_m * 64 + mi * 16 + g;
        const int row1 = row0 + 8;
        #pragma unroll
        for (int ni = 0; ni < 4; ++ni) {
            const int col = bn + warp_n * 32 + ni * 8 + 2 * tg;
            const float bx = bias[col], by = bias[col + 1];
            if (row0 < M) {
                float2 v = {acc[mi][ni][0] + bx, acc[mi][ni][1] + by};
                *reinterpret_cast<float2*>(C + (size_t)row0 * N + col) = v;
            }
            if (row1 < M) {
                float2 v = {acc[mi][ni][2] + bx, acc[mi][ni][3] + by};
                *reinterpret_cast<float2*>(C + (size_t)row1 * N + col) = v;
            }
        }
    }
}

// ---------------- sampling + fused 16-way softmax ---------------------------
__global__ __launch_bounds__(256) void sample_kernel(
    const float* __restrict__ refp)   // [B, LQ, 4, 2]
{
    __shared__ __align__(16) float sw[NH][16][4];  // corner weights (incl. attn wt)
    __shared__ __align__(16) int   si[NH][16][4];  // clamped token indices

    const int bq = blockIdx.x;              // 0 .. B*LQ-1
    const int b  = (bq >= LQ) ? 1 : 0;
    const int h  = threadIdx.x >> 5;
    const int lane = threadIdx.x & 31;

    float logit = -INFINITY;
    if (lane < 16) logit = g_logits[((unsigned)bq * NH + h) * 16 + lane];
    float m = logit;
    #pragma unroll
    for (int o = 16; o > 0; o >>= 1) m = fmaxf(m, __shfl_xor_sync(0xffffffffu, m, o));
    float e = (lane < 16) ? __expf(logit - m) : 0.f;
    float s = e;
    #pragma unroll
    for (int o = 16; o > 0; o >>= 1) s += __shfl_xor_sync(0xffffffffu, s, o);
    const float wt = e / s;

    if (lane < 16) {
        const int LH[4] = {100, 50, 25, 13};
        const int LS[4] = {0, 10000, 12500, 13125};
        const int l = lane >> 2;
        const int w = LH[l], hh = LH[l], s0 = LS[l];
        const float lw = (float)w, lh = (float)hh;

        const float2 off = *reinterpret_cast<const float2*>(
            g_offs + (((unsigned)bq * NH + h) * 16 + lane) * 2);
        const float2 rp = *reinterpret_cast<const float2*>(refp + (unsigned)bq * 8 + l * 2);

        const float x = (rp.x + off.x / lw) * lw - 0.5f;
        const float y = (rp.y + off.y / lh) * lh - 0.5f;
        const float fx = floorf(x), fy = floorf(y);
        const float tx = x - fx, ty = y - fy;
        const int jx = (int)fx, jy = (int)fy;

        const bool xv0 = (jx >= 0) && (jx < w);
        const bool xv1 = (jx + 1 >= 0) && (jx + 1 < w);
        const bool yv0 = (jy >= 0) && (jy < hh);
        const bool yv1 = (jy + 1 >= 0) && (jy + 1 < hh);

        const int cx0 = min(max(jx, 0), w - 1);
        const int cx1 = min(max(jx + 1, 0), w - 1);
        const int cy0 = min(max(jy, 0), hh - 1);
        const int cy1 = min(max(jy + 1, 0), hh - 1);

        const float wx1 = tx, wx0 = 1.f - tx;
        const float wy1 = ty, wy0 = 1.f - ty;

        sw[h][lane][0] = (xv0 && yv0) ? wt * wx0 * wy0 : 0.f;
        sw[h][lane][1] = (xv1 && yv0) ? wt * wx1 * wy0 : 0.f;
        sw[h][lane][2] = (xv0 && yv1) ? wt * wx0 * wy1 : 0.f;
        sw[h][lane][3] = (xv1 && yv1) ? wt * wx1 * wy1 : 0.f;

        si[h][lane][0] = s0 + cy0 * w + cx0;
        si[h][lane][1] = s0 + cy0 * w + cx1;
        si[h][lane][2] = s0 + cy1 * w + cx0;
        si[h][lane][3] = s0 + cy1 * w + cx1;
    }
    __syncwarp();

    const float* __restrict__ vb =
        g_value + ((unsigned)b * LEN_IN) * DM + h * HD + lane;

    float acc0 = 0.f, acc1 = 0.f;
    #pragma unroll
    for (int i = 0; i < 16; ++i) {
        const float4 wv = *reinterpret_cast<const float4*>(sw[h][i]);
        const int4   iv = *reinterpret_cast<const int4*>(si[h][i]);
        acc0 += wv.x * __ldg(vb + (unsigned)iv.x * DM);
        acc1 += wv.y * __ldg(vb + (unsigned)iv.y * DM);
        acc0 += wv.z * __ldg(vb + (unsigned)iv.z * DM);
        acc1 += wv.w * __ldg(vb + (unsigned)iv.w * DM);
    }
    g_acc[(unsigned)bq * DM + h * HD + lane] = acc0 + acc1;
}

// ---------------- launch ----------------------------------------------------
extern "C" void kernel_launch(void* const* d_in, const int* in_sizes, int n_in,
                              void* d_out, int out_size)
{
    const float* query  = (const float*)d_in[0];
    const float* refp   = (const float*)d_in[1];
    const float* inputf = (const float*)d_in[2];
    // d_in[3] = input_spatial_shapes (compile-time constants)
    const float* Wv   = (const float*)d_in[4];
    const float* bv   = (const float*)d_in[5];
    const float* Woff = (const float*)d_in[6];
    const float* boff = (const float*)d_in[7];
    const float* Wa   = (const float*)d_in[8];
    const float* ba   = (const float*)d_in[9];
    const float* Wout = (const float*)d_in[10];
    const float* bout = (const float*)d_in[11];
    float* out = (float*)d_out;

    float *valuep, *offsp, *logitsp, *accp;
    cudaGetSymbolAddress((void**)&valuep,  g_value);
    cudaGetSymbolAddress((void**)&offsp,   g_offs);
    cudaGetSymbolAddress((void**)&logitsp, g_logits);
    cudaGetSymbolAddress((void**)&accp,    g_acc);

    const int M = MROWS;
    const dim3 blk(256);
    const dim3 grid256(DM / 128, (M + 127) / 128);     // N = 256
    const dim3 grid128(1, (M + 127) / 128);            // N = 128

    // 1. value = input_flatten @ W_value + b_value
    mma_gemm_kernel<<<grid256, blk>>>(inputf, Wv, bv, valuep, M, DM, DM);
    // 2. offs = query @ W_off + b_off
    mma_gemm_kernel<<<grid256, blk>>>(query, Woff, boff, offsp, M, DM, DM);
    // 3. logits = query @ W_attn + b_attn
    mma_gemm_kernel<<<grid128, blk>>>(query, Wa, ba, logitsp, M, 128, DM);
    // 4. softmax + bilinear sampling -> acc
    sample_kernel<<<BATCH * LQ, 256>>>(refp);
    // 5. out = acc @ W_out + b_out
    mma_gemm_kernel<<<grid256, blk>>>(accp, Wout, bout, out, M, DM, DM);
}

// round 4
// speedup vs baseline: 1.4923x; 1.4923x over previous
#include <cuda_runtime.h>
#include <math.h>
#include <stdint.h>

#define BATCH 2
#define LQ 13294
#define LEN_IN 13294
#define DM 256
#define NH 8
#define HD 32
#define MROWS (BATCH * LQ)   // 26588
#define MPAD  26624          // 208 * 128
#define SPK   512            // packed floats per row (2 * K)

// ---------------- scratch (device globals; no allocations allowed) ----------
__device__ float g_value[(size_t)BATCH * LEN_IN * DM];   // [B, LEN_IN, NH, HD]
__device__ float g_offs[(size_t)BATCH * LQ * DM];        // [B, LQ, NH, 16, 2]
__device__ float g_logits[(size_t)BATCH * LQ * NH * 16]; // [B, LQ, NH, 16]
__device__ float g_acc[(size_t)BATCH * LQ * DM];         // [B, LQ, NH, HD]

__device__ float g_Apack[(size_t)MPAD * SPK];            // inputf pack, reused for acc
__device__ float g_Qpack[(size_t)MPAD * SPK];            // query pack
__device__ float g_Wvp[256 * SPK];
__device__ float g_Woffp[256 * SPK];
__device__ float g_Wap[128 * SPK];
__device__ float g_Woutp[256 * SPK];

// ---------------- helpers ---------------------------------------------------
__device__ __forceinline__ unsigned f2tf(float x) {
    unsigned r;
    asm("cvt.rna.tf32.f32 %0, %1;" : "=r"(r) : "f"(x));
    return r;
}

__device__ __forceinline__ void mma_tf32(float* d,
    unsigned a0, unsigned a1, unsigned a2, unsigned a3,
    unsigned b0, unsigned b1)
{
    asm volatile(
        "mma.sync.aligned.m16n8k8.row.col.f32.tf32.tf32.f32 "
        "{%0,%1,%2,%3}, {%4,%5,%6,%7}, {%8,%9}, {%0,%1,%2,%3};"
        : "+f"(d[0]), "+f"(d[1]), "+f"(d[2]), "+f"(d[3])
        : "r"(a0), "r"(a1), "r"(a2), "r"(a3), "r"(b0), "r"(b1));
}

__device__ __forceinline__ void cpa16(uint32_t dst, const void* src) {
    asm volatile("cp.async.ca.shared.global [%0], [%1], 16;" :: "r"(dst), "l"(src));
}
#define CPA_COMMIT() asm volatile("cp.async.commit_group;")

__device__ __forceinline__ float4 pack_hilo(float x0, float x1) {
    const unsigned h0 = f2tf(x0), h1 = f2tf(x1);
    float4 q;
    q.x = __uint_as_float(h0);
    q.y = __uint_as_float(h1);
    q.z = __uint_as_float(f2tf(x0 - __uint_as_float(h0)));
    q.w = __uint_as_float(f2tf(x1 - __uint_as_float(h1)));
    return q;
}

// ---------------- prepack kernels -------------------------------------------
// A [M,256] row-major -> Ap quads: idx t = row*128 + s*4 + tg
//   quad = {hi A[row][s8+tg], hi A[row][s8+tg+4], lo..., lo...}
__global__ __launch_bounds__(256) void prepack_A(
    const float* __restrict__ A, float* __restrict__ Ap, int M)
{
    const unsigned t = blockIdx.x * 256 + threadIdx.x;   // < MPAD*128
    const unsigned row = t >> 7, rem = t & 127;
    const unsigned s = rem >> 2, tg = rem & 3;
    float x0 = 0.f, x1 = 0.f;
    if (row < (unsigned)M) {
        const float* a = A + (size_t)row * 256 + s * 8 + tg;
        x0 = a[0];
        x1 = a[4];
    }
    reinterpret_cast<float4*>(Ap)[t] = pack_hilo(x0, x1);
}

// B [256,N] row-major -> Bp quads: idx t = col*128 + s*4 + tg
//   quad = {hi B[s8+tg][col], hi B[s8+tg+4][col], lo..., lo...}
__global__ __launch_bounds__(256) void prepack_B(
    const float* __restrict__ B, float* __restrict__ Bp, int N)
{
    const unsigned t = blockIdx.x * 256 + threadIdx.x;   // < N*128
    const unsigned col = t >> 7, rem = t & 127;
    const unsigned s = rem >> 2, tg = rem & 3;
    const float x0 = B[(s * 8 + tg) * N + col];
    const float x1 = B[(s * 8 + tg + 4) * N + col];
    reinterpret_cast<float4*>(Bp)[t] = pack_hilo(x0, x1);
}

// ---------------- tensor-core GEMM (3xTF32, prepacked operands) -------------
// BM=BN=128, BK=16, 256 threads (8 warps: 2 M x 4 N), warp tile 64x32.
// smem: double-buffered A/B tiles, row stride 48 words (conflict-free).
#define RS 48
#define TILE_WORDS (128 * RS)    // 6144 floats = 24 KB
#define GSMEM_BYTES (4 * TILE_WORDS * 4)   // 96 KB

__global__ __launch_bounds__(256, 2) void mma_gemm_kernel(
    const float* __restrict__ Ap, const float* __restrict__ Bp,
    const float* __restrict__ bias, float* __restrict__ C,
    int M, int N)
{
    extern __shared__ float smem[];  // [buf][A|B][TILE_WORDS]

    const int tid = threadIdx.x;
    const int lane = tid & 31;
    const int wid = tid >> 5;
    const int warp_m = wid & 1;
    const int warp_n = wid >> 1;
    const int g  = lane >> 2;
    const int tg = lane & 3;
    const int bm = blockIdx.y * 128;
    const int bn = blockIdx.x * 128;

    // loader mapping: 1024 quads per tile, 4 per thread
    const int lrow0 = tid >> 3;       // 0..31 (+32 per pass)
    const int lf    = tid & 7;        // quad-in-row (s_local*4 + tg)

    const uint32_t smem_u32 = (uint32_t)__cvta_generic_to_shared(smem);

    const int NCH = 16;   // K/BK = 256/16

    float acc[4][4][4];
    #pragma unroll
    for (int i = 0; i < 4; ++i)
        #pragma unroll
        for (int j = 0; j < 4; ++j)
            #pragma unroll
            for (int e = 0; e < 4; ++e) acc[i][j][e] = 0.f;

    // ---- async tile loader: chunk c covers packed floats [c*32, c*32+32) per row
    auto load_tile = [&](int buf, int c) {
        const uint32_t abase = smem_u32 + (uint32_t)(buf * 2 * TILE_WORDS) * 4;
        const uint32_t bbase = abase + (uint32_t)TILE_WORDS * 4;
        #pragma unroll
        for (int p = 0; p < 4; ++p) {
            const int row = lrow0 + p * 32;
            const float* asrc = Ap + (size_t)(bm + row) * SPK + c * 32 + lf * 4;
            cpa16(abase + (uint32_t)(row * RS + lf * 4) * 4, asrc);
        }
        #pragma unroll
        for (int p = 0; p < 4; ++p) {
            const int col = lrow0 + p * 32;
            const float* bsrc = Bp + (size_t)(bn + col) * SPK + c * 32 + lf * 4;
            cpa16(bbase + (uint32_t)(col * RS + lf * 4) * 4, bsrc);
        }
    };

    load_tile(0, 0);
    CPA_COMMIT();

    for (int c = 0; c < NCH; ++c) {
        const int cur = c & 1;
        if (c + 1 < NCH) {
            load_tile(cur ^ 1, c + 1);
            CPA_COMMIT();
            asm volatile("cp.async.wait_group 1;");
        } else {
            asm volatile("cp.async.wait_group 0;");
        }
        __syncthreads();

        const float* As_ = smem + cur * 2 * TILE_WORDS;
        const float* Bs_ = As_ + TILE_WORDS;

        #pragma unroll
        for (int s = 0; s < 2; ++s) {
            float4 bf[4];
            #pragma unroll
            for (int ni = 0; ni < 4; ++ni)
                bf[ni] = *reinterpret_cast<const float4*>(
                    Bs_ + (warp_n * 32 + ni * 8 + g) * RS + s * 16 + tg * 4);

            #pragma unroll
            for (int mi = 0; mi < 4; ++mi) {
                const float4 a0 = *reinterpret_cast<const float4*>(
                    As_ + (warp_m * 64 + mi * 16 + g) * RS + s * 16 + tg * 4);
                const float4 a1 = *reinterpret_cast<const float4*>(
                    As_ + (warp_m * 64 + mi * 16 + g + 8) * RS + s * 16 + tg * 4);
                const unsigned ah0 = __float_as_uint(a0.x);
                const unsigned ah1 = __float_as_uint(a1.x);
                const unsigned ah2 = __float_as_uint(a0.y);
                const unsigned ah3 = __float_as_uint(a1.y);
                const unsigned al0 = __float_as_uint(a0.z);
                const unsigned al1 = __float_as_uint(a1.z);
                const unsigned al2 = __float_as_uint(a0.w);
                const unsigned al3 = __float_as_uint(a1.w);
                #pragma unroll
                for (int ni = 0; ni < 4; ++ni) {
                    const unsigned bh0 = __float_as_uint(bf[ni].x);
                    const unsigned bh1 = __float_as_uint(bf[ni].y);
                    const unsigned bl0 = __float_as_uint(bf[ni].z);
                    const unsigned bl1 = __float_as_uint(bf[ni].w);
                    mma_tf32(acc[mi][ni], ah0, ah1, ah2, ah3, bh0, bh1);
                    mma_tf32(acc[mi][ni], ah0, ah1, ah2, ah3, bl0, bl1);
                    mma_tf32(acc[mi][ni], al0, al1, al2, al3, bh0, bh1);
                }
            }
        }
        __syncthreads();
    }

    // ---- epilogue ----
    #pragma unroll
    for (int mi = 0; mi < 4; ++mi) {
        const int row0 = bm + warp_m * 64 + mi * 16 + g;
        const int row1 = row0 + 8;
        #pragma unroll
        for (int ni = 0; ni < 4; ++ni) {
            const int col = bn + warp_n * 32 + ni * 8 + 2 * tg;
            const float bx = bias[col], by = bias[col + 1];
            if (row0 < M) {
                float2 v = {acc[mi][ni][0] + bx, acc[mi][ni][1] + by};
                *reinterpret_cast<float2*>(C + (size_t)row0 * N + col) = v;
            }
            if (row1 < M) {
                float2 v = {acc[mi][ni][2] + bx, acc[mi][ni][3] + by};
                *reinterpret_cast<float2*>(C + (size_t)row1 * N + col) = v;
            }
        }
    }
}

// ---------------- sampling + fused 16-way softmax ---------------------------
__global__ __launch_bounds__(256) void sample_kernel(
    const float* __restrict__ refp)   // [B, LQ, 4, 2]
{
    __shared__ __align__(16) float sw[NH][16][4];
    __shared__ __align__(16) int   si[NH][16][4];

    const int bq = blockIdx.x;
    const int b  = (bq >= LQ) ? 1 : 0;
    const int h  = threadIdx.x >> 5;
    const int lane = threadIdx.x & 31;

    float logit = -INFINITY;
    if (lane < 16) logit = g_logits[((unsigned)bq * NH + h) * 16 + lane];
    float m = logit;
    #pragma unroll
    for (int o = 16; o > 0; o >>= 1) m = fmaxf(m, __shfl_xor_sync(0xffffffffu, m, o));
    float e = (lane < 16) ? __expf(logit - m) : 0.f;
    float s = e;
    #pragma unroll
    for (int o = 16; o > 0; o >>= 1) s += __shfl_xor_sync(0xffffffffu, s, o);
    const float wt = e / s;

    if (lane < 16) {
        const int LH[4] = {100, 50, 25, 13};
        const int LS[4] = {0, 10000, 12500, 13125};
        const int l = lane >> 2;
        const int w = LH[l], hh = LH[l], s0 = LS[l];
        const float lw = (float)w, lh = (float)hh;

        const float2 off = *reinterpret_cast<const float2*>(
            g_offs + (((unsigned)bq * NH + h) * 16 + lane) * 2);
        const float2 rp = *reinterpret_cast<const float2*>(refp + (unsigned)bq * 8 + l * 2);

        const float x = (rp.x + off.x / lw) * lw - 0.5f;
        const float y = (rp.y + off.y / lh) * lh - 0.5f;
        const float fx = floorf(x), fy = floorf(y);
        const float tx = x - fx, ty = y - fy;
        const int jx = (int)fx, jy = (int)fy;

        const bool xv0 = (jx >= 0) && (jx < w);
        const bool xv1 = (jx + 1 >= 0) && (jx + 1 < w);
        const bool yv0 = (jy >= 0) && (jy < hh);
        const bool yv1 = (jy + 1 >= 0) && (jy + 1 < hh);

        const int cx0 = min(max(jx, 0), w - 1);
        const int cx1 = min(max(jx + 1, 0), w - 1);
        const int cy0 = min(max(jy, 0), hh - 1);
        const int cy1 = min(max(jy + 1, 0), hh - 1);

        const float wx1 = tx, wx0 = 1.f - tx;
        const float wy1 = ty, wy0 = 1.f - ty;

        sw[h][lane][0] = (xv0 && yv0) ? wt * wx0 * wy0 : 0.f;
        sw[h][lane][1] = (xv1 && yv0) ? wt * wx1 * wy0 : 0.f;
        sw[h][lane][2] = (xv0 && yv1) ? wt * wx0 * wy1 : 0.f;
        sw[h][lane][3] = (xv1 && yv1) ? wt * wx1 * wy1 : 0.f;

        si[h][lane][0] = s0 + cy0 * w + cx0;
        si[h][lane][1] = s0 + cy0 * w + cx1;
        si[h][lane][2] = s0 + cy1 * w + cx0;
        si[h][lane][3] = s0 + cy1 * w + cx1;
    }
    __syncwarp();

    const float* __restrict__ vb =
        g_value + ((unsigned)b * LEN_IN) * DM + h * HD + lane;

    float acc0 = 0.f, acc1 = 0.f;
    #pragma unroll
    for (int i = 0; i < 16; ++i) {
        const float4 wv = *reinterpret_cast<const float4*>(sw[h][i]);
        const int4   iv = *reinterpret_cast<const int4*>(si[h][i]);
        acc0 += wv.x * __ldg(vb + (unsigned)iv.x * DM);
        acc1 += wv.y * __ldg(vb + (unsigned)iv.y * DM);
        acc0 += wv.z * __ldg(vb + (unsigned)iv.z * DM);
        acc1 += wv.w * __ldg(vb + (unsigned)iv.w * DM);
    }
    g_acc[(unsigned)bq * DM + h * HD + lane] = acc0 + acc1;
}

// ---------------- launch ----------------------------------------------------
extern "C" void kernel_launch(void* const* d_in, const int* in_sizes, int n_in,
                              void* d_out, int out_size)
{
    const float* query  = (const float*)d_in[0];
    const float* refp   = (const float*)d_in[1];
    const float* inputf = (const float*)d_in[2];
    const float* Wv   = (const float*)d_in[4];
    const float* bv   = (const float*)d_in[5];
    const float* Woff = (const float*)d_in[6];
    const float* boff = (const float*)d_in[7];
    const float* Wa   = (const float*)d_in[8];
    const float* ba   = (const float*)d_in[9];
    const float* Wout = (const float*)d_in[10];
    const float* bout = (const float*)d_in[11];
    float* out = (float*)d_out;

    float *valuep, *offsp, *logitsp, *accp;
    float *apackp, *qpackp, *wvp, *woffp, *wap, *woutp;
    cudaGetSymbolAddress((void**)&valuep,  g_value);
    cudaGetSymbolAddress((void**)&offsp,   g_offs);
    cudaGetSymbolAddress((void**)&logitsp, g_logits);
    cudaGetSymbolAddress((void**)&accp,    g_acc);
    cudaGetSymbolAddress((void**)&apackp,  g_Apack);
    cudaGetSymbolAddress((void**)&qpackp,  g_Qpack);
    cudaGetSymbolAddress((void**)&wvp,     g_Wvp);
    cudaGetSymbolAddress((void**)&woffp,   g_Woffp);
    cudaGetSymbolAddress((void**)&wap,     g_Wap);
    cudaGetSymbolAddress((void**)&woutp,   g_Woutp);

    static bool attr_set = false;
    if (!attr_set) {
        cudaFuncSetAttribute(mma_gemm_kernel,
                             cudaFuncAttributeMaxDynamicSharedMemorySize, GSMEM_BYTES);
        attr_set = true;
    }

    const int M = MROWS;
    const dim3 blk(256);
    const dim3 grid256(2, MPAD / 128);   // N = 256
    const dim3 grid128(1, MPAD / 128);   // N = 128

    // prepack
    prepack_A<<<MPAD * 128 / 256, 256>>>(inputf, apackp, M);
    prepack_A<<<MPAD * 128 / 256, 256>>>(query,  qpackp, M);
    prepack_B<<<256 * 128 / 256, 256>>>(Wv,   wvp,   256);
    prepack_B<<<256 * 128 / 256, 256>>>(Woff, woffp, 256);
    prepack_B<<<128 * 128 / 256, 256>>>(Wa,   wap,   128);
    prepack_B<<<256 * 128 / 256, 256>>>(Wout, woutp, 256);

    // 1. value = input_flatten @ W_value + b_value
    mma_gemm_kernel<<<grid256, blk, GSMEM_BYTES>>>(apackp, wvp, bv, valuep, M, 256);
    // 2. offs = query @ W_off + b_off
    mma_gemm_kernel<<<grid256, blk, GSMEM_BYTES>>>(qpackp, woffp, boff, offsp, M, 256);
    // 3. logits = query @ W_attn + b_attn
    mma_gemm_kernel<<<grid128, blk, GSMEM_BYTES>>>(qpackp, wap, ba, logitsp, M, 128);
    // 4. softmax + bilinear sampling -> acc
    sample_kernel<<<BATCH * LQ, 256>>>(refp);
    // 5. out = acc @ W_out + b_out  (reuse Apack buffer for acc)
    prepack_A<<<MPAD * 128 / 256, 256>>>(accp, apackp, M);
    mma_gemm_kernel<<<grid256, blk, GSMEM_BYTES>>>(apackp, woutp, bout, out, M, 256);
}

// round 5
// speedup vs baseline: 2.0532x; 1.3759x over previous
#include <cuda_runtime.h>
#include <cuda_bf16.h>
#include <math.h>
#include <stdint.h>

#define BATCH 2
#define LQ 13294
#define LEN_IN 13294
#define DM 256
#define NH 8
#define HD 32
#define MROWS (BATCH * LQ)   // 26588
#define MPAD  26624          // 208 * 128
#define QPR   64             // packed uint4 quads per row (16 chunks * 4 tg)

// ---------------- scratch (device globals; no allocations allowed) ----------
__device__ float g_value[(size_t)BATCH * LEN_IN * DM];   // [B, LEN_IN, NH, HD]
__device__ float g_offs[(size_t)BATCH * LQ * DM];        // [B, LQ, NH, 16, 2]
__device__ float g_logits[(size_t)BATCH * LQ * NH * 16]; // [B, LQ, NH, 16]
__device__ float g_acc[(size_t)BATCH * LQ * DM];         // [B, LQ, NH, HD]

__device__ uint4 g_Apack[(size_t)MPAD * QPR];            // inputf pack, reused for acc
__device__ uint4 g_Qpack[(size_t)MPAD * QPR];            // query pack
__device__ uint4 g_Wvp[256 * QPR];
__device__ uint4 g_Woffp[256 * QPR];
__device__ uint4 g_Wap[128 * QPR];
__device__ uint4 g_Woutp[256 * QPR];

// ---------------- helpers ---------------------------------------------------
__device__ __forceinline__ void mma_bf16(float* d,
    unsigned a0, unsigned a1, unsigned a2, unsigned a3,
    unsigned b0, unsigned b1)
{
    asm volatile(
        "mma.sync.aligned.m16n8k16.row.col.f32.bf16.bf16.f32 "
        "{%0,%1,%2,%3}, {%4,%5,%6,%7}, {%8,%9}, {%0,%1,%2,%3};"
        : "+f"(d[0]), "+f"(d[1]), "+f"(d[2]), "+f"(d[3])
        : "r"(a0), "r"(a1), "r"(a2), "r"(a3), "r"(b0), "r"(b1));
}

__device__ __forceinline__ void cpa16(uint32_t dst, const void* src) {
    asm volatile("cp.async.ca.shared.global [%0], [%1], 16;" :: "r"(dst), "l"(src));
}
#define CPA_COMMIT() asm volatile("cp.async.commit_group;")

__device__ __forceinline__ unsigned pack_hi2(float x0, float x1,
                                             float& l0, float& l1) {
    const __nv_bfloat16 h0 = __float2bfloat16_rn(x0);
    const __nv_bfloat16 h1 = __float2bfloat16_rn(x1);
    l0 = x0 - __bfloat162float(h0);
    l1 = x1 - __bfloat162float(h1);
    __nv_bfloat162 p; p.x = h0; p.y = h1;
    return *reinterpret_cast<unsigned*>(&p);
}
__device__ __forceinline__ unsigned pack_lo2(float l0, float l1) {
    __nv_bfloat162 p;
    p.x = __float2bfloat16_rn(l0);
    p.y = __float2bfloat16_rn(l1);
    return *reinterpret_cast<unsigned*>(&p);
}
__device__ __forceinline__ uint4 pack_quad(float x0, float x1, float x2, float x3) {
    float l0, l1, l2, l3;
    uint4 q;
    q.x = pack_hi2(x0, x1, l0, l1);   // hi pair (k=2tg, 2tg+1)
    q.y = pack_hi2(x2, x3, l2, l3);   // hi pair (k=2tg+8, 2tg+9)
    q.z = pack_lo2(l0, l1);
    q.w = pack_lo2(l2, l3);
    return q;
}

// ---------------- prepack kernels -------------------------------------------
// A [M,256] row-major. quad index: row*64 + c*4 + tg (c = k16 chunk)
__global__ __launch_bounds__(256) void prepack_A(
    const float* __restrict__ A, uint4* __restrict__ Ap, int M)
{
    const unsigned t = blockIdx.x * 256 + threadIdx.x;   // < MPAD*64
    const unsigned row = t >> 6;
    const unsigned c = (t >> 2) & 15, tg = t & 3;
    float x0 = 0.f, x1 = 0.f, x2 = 0.f, x3 = 0.f;
    if (row < (unsigned)M) {
        const float* a = A + (size_t)row * 256 + c * 16 + 2 * tg;
        x0 = a[0]; x1 = a[1]; x2 = a[8]; x3 = a[9];
    }
    Ap[t] = pack_quad(x0, x1, x2, x3);
}

// B [256,N] row-major -> col-major quads: col*64 + c*4 + tg
__global__ __launch_bounds__(256) void prepack_B(
    const float* __restrict__ B, uint4* __restrict__ Bp, int N)
{
    const unsigned t = blockIdx.x * 256 + threadIdx.x;   // < N*64
    const unsigned col = t >> 6;
    const unsigned c = (t >> 2) & 15, tg = t & 3;
    const unsigned k = c * 16 + 2 * tg;
    const float x0 = B[(k + 0) * N + col];
    const float x1 = B[(k + 1) * N + col];
    const float x2 = B[(k + 8) * N + col];
    const float x3 = B[(k + 9) * N + col];
    Bp[t] = pack_quad(x0, x1, x2, x3);
}

// ---------------- tensor-core GEMM (3xBF16 split, prepacked) ----------------
// BM=BN=128, BK=32 (2 k16 steps), 256 threads (8 warps: 2 M x 4 N), warp 64x32.
// smem: row stride 12 quads (192 B: 8 payload + 4 pad) -> conflict-free LDS.128.
#define RQ 12
#define TILE_QUADS (128 * RQ)                 // 1536 quads = 24 KB
#define GSMEM_BYTES (4 * TILE_QUADS * 16)     // 96 KB (A+B, double buffered)

__global__ __launch_bounds__(256, 2) void mma_gemm_kernel(
    const uint4* __restrict__ Ap, const uint4* __restrict__ Bp,
    const float* __restrict__ bias, float* __restrict__ C,
    int M, int N)
{
    extern __shared__ uint4 smem[];  // [buf][A|B][TILE_QUADS]

    const int tid = threadIdx.x;
    const int lane = tid & 31;
    const int wid = tid >> 5;
    const int warp_m = wid & 1;
    const int warp_n = wid >> 1;
    const int g  = lane >> 2;
    const int tg = lane & 3;
    const int bm = blockIdx.y * 128;
    const int bn = blockIdx.x * 128;

    // loader: 1024 quads per operand tile, 4 per thread
    const int lrow0 = tid >> 3;   // 0..31 (+32 per pass)
    const int lf    = tid & 7;    // quad-in-row 0..7

    const uint32_t smem_u32 = (uint32_t)__cvta_generic_to_shared(smem);
    const int NCH = 8;            // K/BK = 256/32

    float acc[4][4][4];
    #pragma unroll
    for (int i = 0; i < 4; ++i)
        #pragma unroll
        for (int j = 0; j < 4; ++j)
            #pragma unroll
            for (int e = 0; e < 4; ++e) acc[i][j][e] = 0.f;

    auto load_tile = [&](int buf, int c) {
        const uint32_t abase = smem_u32 + (uint32_t)(buf * 2 * TILE_QUADS) * 16;
        const uint32_t bbase = abase + (uint32_t)TILE_QUADS * 16;
        #pragma unroll
        for (int p = 0; p < 4; ++p) {
            const int row = lrow0 + p * 32;
            cpa16(abase + (uint32_t)(row * RQ + lf) * 16,
                  Ap + (size_t)(bm + row) * QPR + c * 8 + lf);
        }
        #pragma unroll
        for (int p = 0; p < 4; ++p) {
            const int col = lrow0 + p * 32;
            cpa16(bbase + (uint32_t)(col * RQ + lf) * 16,
                  Bp + (size_t)(bn + col) * QPR + c * 8 + lf);
        }
    };

    load_tile(0, 0);
    CPA_COMMIT();

    for (int c = 0; c < NCH; ++c) {
        const int cur = c & 1;
        if (c + 1 < NCH) {
            load_tile(cur ^ 1, c + 1);
            CPA_COMMIT();
            asm volatile("cp.async.wait_group 1;");
        } else {
            asm volatile("cp.async.wait_group 0;");
        }
        __syncthreads();

        const uint4* As_ = smem + cur * 2 * TILE_QUADS;
        const uint4* Bs_ = As_ + TILE_QUADS;

        #pragma unroll
        for (int cl = 0; cl < 2; ++cl) {      // 2 k16 steps per chunk
            const int qoff = cl * 4 + tg;
            uint4 bf[4];
            #pragma unroll
            for (int ni = 0; ni < 4; ++ni)
                bf[ni] = Bs_[(warp_n * 32 + ni * 8 + g) * RQ + qoff];

            #pragma unroll
            for (int mi = 0; mi < 4; ++mi) {
                const uint4 a0 = As_[(warp_m * 64 + mi * 16 + g) * RQ + qoff];
                const uint4 a1 = As_[(warp_m * 64 + mi * 16 + g + 8) * RQ + qoff];
                // hi frags: a0.x=(g,k2tg) a1.x=(g+8,k2tg) a0.y=(g,k2tg+8) a1.y=(g+8,..)
                #pragma unroll
                for (int ni = 0; ni < 4; ++ni) {
                    mma_bf16(acc[mi][ni], a0.x, a1.x, a0.y, a1.y, bf[ni].x, bf[ni].y);
                    mma_bf16(acc[mi][ni], a0.x, a1.x, a0.y, a1.y, bf[ni].z, bf[ni].w);
                    mma_bf16(acc[mi][ni], a0.z, a1.z, a0.w, a1.w, bf[ni].x, bf[ni].y);
                }
            }
        }
        __syncthreads();
    }

    // ---- epilogue ----
    #pragma unroll
    for (int mi = 0; mi < 4; ++mi) {
        const int row0 = bm + warp_m * 64 + mi * 16 + g;
        const int row1 = row0 + 8;
        #pragma unroll
        for (int ni = 0; ni < 4; ++ni) {
            const int col = bn + warp_n * 32 + ni * 8 + 2 * tg;
            const float bx = bias[col], by = bias[col + 1];
            if (row0 < M) {
                float2 v = {acc[mi][ni][0] + bx, acc[mi][ni][1] + by};
                *reinterpret_cast<float2*>(C + (size_t)row0 * N + col) = v;
            }
            if (row1 < M) {
                float2 v = {acc[mi][ni][2] + bx, acc[mi][ni][3] + by};
                *reinterpret_cast<float2*>(C + (size_t)row1 * N + col) = v;
            }
        }
    }
}

// ---------------- sampling + fused 16-way softmax ---------------------------
__global__ __launch_bounds__(256) void sample_kernel(
    const float* __restrict__ refp)   // [B, LQ, 4, 2]
{
    __shared__ __align__(16) float sw[NH][16][4];
    __shared__ __align__(16) int   si[NH][16][4];

    const int bq = blockIdx.x;
    const int b  = (bq >= LQ) ? 1 : 0;
    const int h  = threadIdx.x >> 5;
    const int lane = threadIdx.x & 31;

    float logit = -INFINITY;
    if (lane < 16) logit = g_logits[((unsigned)bq * NH + h) * 16 + lane];
    float m = logit;
    #pragma unroll
    for (int o = 16; o > 0; o >>= 1) m = fmaxf(m, __shfl_xor_sync(0xffffffffu, m, o));
    float e = (lane < 16) ? __expf(logit - m) : 0.f;
    float s = e;
    #pragma unroll
    for (int o = 16; o > 0; o >>= 1) s += __shfl_xor_sync(0xffffffffu, s, o);
    const float wt = e / s;

    if (lane < 16) {
        const int LH[4] = {100, 50, 25, 13};
        const int LS[4] = {0, 10000, 12500, 13125};
        const int l = lane >> 2;
        const int w = LH[l], hh = LH[l], s0 = LS[l];
        const float lw = (float)w, lh = (float)hh;

        const float2 off = *reinterpret_cast<const float2*>(
            g_offs + (((unsigned)bq * NH + h) * 16 + lane) * 2);
        const float2 rp = *reinterpret_cast<const float2*>(refp + (unsigned)bq * 8 + l * 2);

        const float x = (rp.x + off.x / lw) * lw - 0.5f;
        const float y = (rp.y + off.y / lh) * lh - 0.5f;
        const float fx = floorf(x), fy = floorf(y);
        const float tx = x - fx, ty = y - fy;
        const int jx = (int)fx, jy = (int)fy;

        const bool xv0 = (jx >= 0) && (jx < w);
        const bool xv1 = (jx + 1 >= 0) && (jx + 1 < w);
        const bool yv0 = (jy >= 0) && (jy < hh);
        const bool yv1 = (jy + 1 >= 0) && (jy + 1 < hh);

        const int cx0 = min(max(jx, 0), w - 1);
        const int cx1 = min(max(jx + 1, 0), w - 1);
        const int cy0 = min(max(jy, 0), hh - 1);
        const int cy1 = min(max(jy + 1, 0), hh - 1);

        const float wx1 = tx, wx0 = 1.f - tx;
        const float wy1 = ty, wy0 = 1.f - ty;

        sw[h][lane][0] = (xv0 && yv0) ? wt * wx0 * wy0 : 0.f;
        sw[h][lane][1] = (xv1 && yv0) ? wt * wx1 * wy0 : 0.f;
        sw[h][lane][2] = (xv0 && yv1) ? wt * wx0 * wy1 : 0.f;
        sw[h][lane][3] = (xv1 && yv1) ? wt * wx1 * wy1 : 0.f;

        si[h][lane][0] = s0 + cy0 * w + cx0;
        si[h][lane][1] = s0 + cy0 * w + cx1;
        si[h][lane][2] = s0 + cy1 * w + cx0;
        si[h][lane][3] = s0 + cy1 * w + cx1;
    }
    __syncwarp();

    const float* __restrict__ vb =
        g_value + ((unsigned)b * LEN_IN) * DM + h * HD + lane;

    float acc0 = 0.f, acc1 = 0.f;
    #pragma unroll
    for (int i = 0; i < 16; ++i) {
        const float4 wv = *reinterpret_cast<const float4*>(sw[h][i]);
        const int4   iv = *reinterpret_cast<const int4*>(si[h][i]);
        acc0 += wv.x * __ldg(vb + (unsigned)iv.x * DM);
        acc1 += wv.y * __ldg(vb + (unsigned)iv.y * DM);
        acc0 += wv.z * __ldg(vb + (unsigned)iv.z * DM);
        acc1 += wv.w * __ldg(vb + (unsigned)iv.w * DM);
    }
    g_acc[(unsigned)bq * DM + h * HD + lane] = acc0 + acc1;
}

// ---------------- launch ----------------------------------------------------
extern "C" void kernel_launch(void* const* d_in, const int* in_sizes, int n_in,
                              void* d_out, int out_size)
{
    const float* query  = (const float*)d_in[0];
    const float* refp   = (const float*)d_in[1];
    const float* inputf = (const float*)d_in[2];
    const float* Wv   = (const float*)d_in[4];
    const float* bv   = (const float*)d_in[5];
    const float* Woff = (const float*)d_in[6];
    const float* boff = (const float*)d_in[7];
    const float* Wa   = (const float*)d_in[8];
    const float* ba   = (const float*)d_in[9];
    const float* Wout = (const float*)d_in[10];
    const float* bout = (const float*)d_in[11];
    float* out = (float*)d_out;

    float *valuep, *offsp, *logitsp, *accp;
    uint4 *apackp, *qpackp, *wvp, *woffp, *wap, *woutp;
    cudaGetSymbolAddress((void**)&valuep,  g_value);
    cudaGetSymbolAddress((void**)&offsp,   g_offs);
    cudaGetSymbolAddress((void**)&logitsp, g_logits);
    cudaGetSymbolAddress((void**)&accp,    g_acc);
    cudaGetSymbolAddress((void**)&apackp,  g_Apack);
    cudaGetSymbolAddress((void**)&qpackp,  g_Qpack);
    cudaGetSymbolAddress((void**)&wvp,     g_Wvp);
    cudaGetSymbolAddress((void**)&woffp,   g_Woffp);
    cudaGetSymbolAddress((void**)&wap,     g_Wap);
    cudaGetSymbolAddress((void**)&woutp,   g_Woutp);

    static bool attr_set = false;
    if (!attr_set) {
        cudaFuncSetAttribute(mma_gemm_kernel,
                             cudaFuncAttributeMaxDynamicSharedMemorySize, GSMEM_BYTES);
        attr_set = true;
    }

    const int M = MROWS;
    const dim3 blk(256);
    const dim3 grid256(2, MPAD / 128);   // N = 256
    const dim3 grid128(1, MPAD / 128);   // N = 128

    // prepack (A buffers: MPAD*64 quads; B buffers: N*64 quads)
    prepack_A<<<MPAD * 64 / 256, 256>>>(inputf, apackp, M);
    prepack_A<<<MPAD * 64 / 256, 256>>>(query,  qpackp, M);
    prepack_B<<<256 * 64 / 256, 256>>>(Wv,   wvp,   256);
    prepack_B<<<256 * 64 / 256, 256>>>(Woff, woffp, 256);
    prepack_B<<<128 * 64 / 256, 256>>>(Wa,   wap,   128);
    prepack_B<<<256 * 64 / 256, 256>>>(Wout, woutp, 256);

    // 1. value = input_flatten @ W_value + b_value
    mma_gemm_kernel<<<grid256, blk, GSMEM_BYTES>>>(apackp, wvp, bv, valuep, M, 256);
    // 2. offs = query @ W_off + b_off
    mma_gemm_kernel<<<grid256, blk, GSMEM_BYTES>>>(qpackp, woffp, boff, offsp, M, 256);
    // 3. logits = query @ W_attn + b_attn
    mma_gemm_kernel<<<grid128, blk, GSMEM_BYTES>>>(qpackp, wap, ba, logitsp, M, 128);
    // 4. softmax + bilinear sampling -> acc
    sample_kernel<<<BATCH * LQ, 256>>>(refp);
    // 5. out = acc @ W_out + b_out  (reuse Apack buffer for acc)
    prepack_A<<<MPAD * 64 / 256, 256>>>(accp, apackp, M);
    mma_gemm_kernel<<<grid256, blk, GSMEM_BYTES>>>(apackp, woutp, bout, out, M, 256);
}

// round 6
// speedup vs baseline: 2.3793x; 1.1588x over previous
#include <cuda_runtime.h>
#include <cuda_bf16.h>
#include <math.h>
#include <stdint.h>

#define BATCH 2
#define LQ 13294
#define LEN_IN 13294
#define DM 256
#define NH 8
#define HD 32
#define MROWS (BATCH * LQ)   // 26588
#define MPAD  26624          // 208 * 128
#define QPR   64             // packed uint4 quads per row (16 chunks * 4 tg)
#define GRID_GEMM 304        // 2 CTAs/SM * 152 SMs (GB300)

// ---------------- scratch (device globals; no allocations allowed) ----------
__device__ float g_value[(size_t)BATCH * LEN_IN * DM];   // [B, LEN_IN, NH, HD]
__device__ float g_offs[(size_t)BATCH * LQ * DM];        // [B, LQ, NH, 16, 2]
__device__ float g_logits[(size_t)BATCH * LQ * NH * 16]; // [B, LQ, NH, 16]

__device__ uint4 g_Apack[(size_t)MPAD * QPR];            // inputf pack, reused for acc
__device__ uint4 g_Qpack[(size_t)MPAD * QPR];            // query pack
__device__ uint4 g_Wvp[256 * QPR];
__device__ uint4 g_Woffp[256 * QPR];
__device__ uint4 g_Wap[128 * QPR];
__device__ uint4 g_Woutp[256 * QPR];

// ---------------- helpers ---------------------------------------------------
__device__ __forceinline__ void mma_bf16(float* d,
    unsigned a0, unsigned a1, unsigned a2, unsigned a3,
    unsigned b0, unsigned b1)
{
    asm volatile(
        "mma.sync.aligned.m16n8k16.row.col.f32.bf16.bf16.f32 "
        "{%0,%1,%2,%3}, {%4,%5,%6,%7}, {%8,%9}, {%0,%1,%2,%3};"
        : "+f"(d[0]), "+f"(d[1]), "+f"(d[2]), "+f"(d[3])
        : "r"(a0), "r"(a1), "r"(a2), "r"(a3), "r"(b0), "r"(b1));
}

__device__ __forceinline__ void cpa16(uint32_t dst, const void* src) {
    asm volatile("cp.async.ca.shared.global [%0], [%1], 16;" :: "r"(dst), "l"(src));
}
#define CPA_COMMIT() asm volatile("cp.async.commit_group;")

__device__ __forceinline__ unsigned pack_hi2(float x0, float x1,
                                             float& l0, float& l1) {
    const __nv_bfloat16 h0 = __float2bfloat16_rn(x0);
    const __nv_bfloat16 h1 = __float2bfloat16_rn(x1);
    l0 = x0 - __bfloat162float(h0);
    l1 = x1 - __bfloat162float(h1);
    __nv_bfloat162 p; p.x = h0; p.y = h1;
    return *reinterpret_cast<unsigned*>(&p);
}
__device__ __forceinline__ unsigned pack_lo2(float l0, float l1) {
    __nv_bfloat162 p;
    p.x = __float2bfloat16_rn(l0);
    p.y = __float2bfloat16_rn(l1);
    return *reinterpret_cast<unsigned*>(&p);
}
__device__ __forceinline__ uint4 pack_quad(float x0, float x1, float x2, float x3) {
    float l0, l1, l2, l3;
    uint4 q;
    q.x = pack_hi2(x0, x1, l0, l1);
    q.y = pack_hi2(x2, x3, l2, l3);
    q.z = pack_lo2(l0, l1);
    q.w = pack_lo2(l2, l3);
    return q;
}

// ---------------- prepack kernels -------------------------------------------
// A [M,256] row-major. quad index: row*64 + c*4 + tg (c = k16 chunk)
__global__ __launch_bounds__(256) void prepack_A_dual(
    const float* __restrict__ A0, const float* __restrict__ A1,
    uint4* __restrict__ P0, uint4* __restrict__ P1)
{
    const unsigned t = blockIdx.x * 256 + threadIdx.x;
    const unsigned HALF = (unsigned)MPAD * 64;
    const float* A = (t < HALF) ? A0 : A1;
    uint4* P = (t < HALF) ? P0 : P1;
    const unsigned lt = (t < HALF) ? t : t - HALF;
    const unsigned row = lt >> 6;
    const unsigned c = (lt >> 2) & 15, tg = lt & 3;
    float x0 = 0.f, x1 = 0.f, x2 = 0.f, x3 = 0.f;
    if (row < (unsigned)MROWS) {
        const float* a = A + (size_t)row * 256 + c * 16 + 2 * tg;
        x0 = a[0]; x1 = a[1]; x2 = a[8]; x3 = a[9];
    }
    P[lt] = pack_quad(x0, x1, x2, x3);
}

// all weights in one launch. B [256,N] row-major -> col-major quads.
__global__ __launch_bounds__(256) void prepack_W_all(
    const float* __restrict__ Wv,  const float* __restrict__ Woff,
    const float* __restrict__ Wa,  const float* __restrict__ Wout,
    uint4* __restrict__ wvp, uint4* __restrict__ woffp,
    uint4* __restrict__ wap, uint4* __restrict__ woutp)
{
    const unsigned t = blockIdx.x * 256 + threadIdx.x;  // < 57344
    const float* B; uint4* Bp; unsigned N, lt;
    if (t < 16384)      { B = Wv;   Bp = wvp;   N = 256; lt = t; }
    else if (t < 32768) { B = Woff; Bp = woffp; N = 256; lt = t - 16384; }
    else if (t < 40960) { B = Wa;   Bp = wap;   N = 128; lt = t - 32768; }
    else                { B = Wout; Bp = woutp; N = 256; lt = t - 40960; }
    const unsigned col = lt >> 6;
    const unsigned c = (lt >> 2) & 15, tg = lt & 3;
    const unsigned k = c * 16 + 2 * tg;
    const float x0 = B[(k + 0) * N + col];
    const float x1 = B[(k + 1) * N + col];
    const float x2 = B[(k + 8) * N + col];
    const float x3 = B[(k + 9) * N + col];
    Bp[lt] = pack_quad(x0, x1, x2, x3);
}

// ---------------- tensor-core GEMM tile (3xBF16 split, prepacked) -----------
// BM=BN=128, BK=32, 256 threads (8 warps: 2 M x 4 N), warp tile 64x32.
#define RQ 12
#define TILE_QUADS (128 * RQ)                 // 1536 quads = 24 KB
#define GSMEM_BYTES (4 * TILE_QUADS * 16)     // 96 KB

struct GemmJob {
    const uint4* Ap;
    const uint4* Bp;
    const float* bias;
    float* C;
    int N;       // 256 or 128
    int ncols;   // N / 128
    int ntiles;  // ncols * 208
};

__device__ __forceinline__ void gemm_tile(
    const uint4* __restrict__ Ap, const uint4* __restrict__ Bp,
    const float* __restrict__ bias, float* __restrict__ C,
    int N, int bm, int bn, uint4* smem)
{
    const int tid = threadIdx.x;
    const int lane = tid & 31;
    const int wid = tid >> 5;
    const int warp_m = wid & 1;
    const int warp_n = wid >> 1;
    const int g  = lane >> 2;
    const int tg = lane & 3;

    const int lrow0 = tid >> 3;   // 0..31 (+32 per pass)
    const int lf    = tid & 7;

    const uint32_t smem_u32 = (uint32_t)__cvta_generic_to_shared(smem);
    const int NCH = 8;

    float acc[4][4][4];
    #pragma unroll
    for (int i = 0; i < 4; ++i)
        #pragma unroll
        for (int j = 0; j < 4; ++j)
            #pragma unroll
            for (int e = 0; e < 4; ++e) acc[i][j][e] = 0.f;

    auto load_tile = [&](int buf, int c) {
        const uint32_t abase = smem_u32 + (uint32_t)(buf * 2 * TILE_QUADS) * 16;
        const uint32_t bbase = abase + (uint32_t)TILE_QUADS * 16;
        #pragma unroll
        for (int p = 0; p < 4; ++p) {
            const int row = lrow0 + p * 32;
            cpa16(abase + (uint32_t)(row * RQ + lf) * 16,
                  Ap + (size_t)(bm + row) * QPR + c * 8 + lf);
        }
        #pragma unroll
        for (int p = 0; p < 4; ++p) {
            const int col = lrow0 + p * 32;
            cpa16(bbase + (uint32_t)(col * RQ + lf) * 16,
                  Bp + (size_t)(bn + col) * QPR + c * 8 + lf);
        }
    };

    load_tile(0, 0);
    CPA_COMMIT();

    for (int c = 0; c < NCH; ++c) {
        const int cur = c & 1;
        if (c + 1 < NCH) {
            load_tile(cur ^ 1, c + 1);
            CPA_COMMIT();
            asm volatile("cp.async.wait_group 1;");
        } else {
            asm volatile("cp.async.wait_group 0;");
        }
        __syncthreads();

        const uint4* As_ = smem + cur * 2 * TILE_QUADS;
        const uint4* Bs_ = As_ + TILE_QUADS;

        #pragma unroll
        for (int cl = 0; cl < 2; ++cl) {
            const int qoff = cl * 4 + tg;
            uint4 bf[4];
            #pragma unroll
            for (int ni = 0; ni < 4; ++ni)
                bf[ni] = Bs_[(warp_n * 32 + ni * 8 + g) * RQ + qoff];

            #pragma unroll
            for (int mi = 0; mi < 4; ++mi) {
                const uint4 a0 = As_[(warp_m * 64 + mi * 16 + g) * RQ + qoff];
                const uint4 a1 = As_[(warp_m * 64 + mi * 16 + g + 8) * RQ + qoff];
                #pragma unroll
                for (int ni = 0; ni < 4; ++ni) {
                    mma_bf16(acc[mi][ni], a0.x, a1.x, a0.y, a1.y, bf[ni].x, bf[ni].y);
                    mma_bf16(acc[mi][ni], a0.x, a1.x, a0.y, a1.y, bf[ni].z, bf[ni].w);
                    mma_bf16(acc[mi][ni], a0.z, a1.z, a0.w, a1.w, bf[ni].x, bf[ni].y);
                }
            }
        }
        __syncthreads();   // also protects smem reuse across tile iterations
    }

    #pragma unroll
    for (int mi = 0; mi < 4; ++mi) {
        const int row0 = bm + warp_m * 64 + mi * 16 + g;
        const int row1 = row0 + 8;
        #pragma unroll
        for (int ni = 0; ni < 4; ++ni) {
            const int col = bn + warp_n * 32 + ni * 8 + 2 * tg;
            const float bx = bias[col], by = bias[col + 1];
            if (row0 < MROWS) {
                float2 v = {acc[mi][ni][0] + bx, acc[mi][ni][1] + by};
                *reinterpret_cast<float2*>(C + (size_t)row0 * N + col) = v;
            }
            if (row1 < MROWS) {
                float2 v = {acc[mi][ni][2] + bx, acc[mi][ni][3] + by};
                *reinterpret_cast<float2*>(C + (size_t)row1 * N + col) = v;
            }
        }
    }
}

// persistent grid-stride GEMM over up to 3 jobs
__global__ __launch_bounds__(256, 2) void fused_gemm_kernel(
    GemmJob j0, GemmJob j1, GemmJob j2, int njobs, int total)
{
    extern __shared__ uint4 smem[];
    for (int t = blockIdx.x; t < total; t += gridDim.x) {
        GemmJob jb = j0;
        int lt = t;
        if (njobs > 1 && lt >= jb.ntiles) {
            lt -= jb.ntiles; jb = j1;
            if (njobs > 2 && lt >= jb.ntiles) { lt -= jb.ntiles; jb = j2; }
        }
        int bm, bn;
        if (jb.ncols == 2) { bm = (lt >> 1) * 128; bn = (lt & 1) * 128; }
        else               { bm = lt * 128;        bn = 0; }
        gemm_tile(jb.Ap, jb.Bp, jb.bias, jb.C, jb.N, bm, bn, smem);
    }
}

// ---------------- sampling + softmax + fused bf16 hi/lo packing -------------
__global__ __launch_bounds__(256) void sample_kernel(
    const float* __restrict__ refp, uint4* __restrict__ AccPack)
{
    __shared__ __align__(16) float sw[NH][16][4];
    __shared__ __align__(16) int   si[NH][16][4];   // byte offsets (idx<<10)
    __shared__ __align__(16) float sacc[256];

    const int bq = blockIdx.x;
    const int b  = (bq >= LQ) ? 1 : 0;
    const int tid = threadIdx.x;
    const int h  = tid >> 5;
    const int lane = tid & 31;

    float logit = -INFINITY;
    if (lane < 16) logit = g_logits[((unsigned)bq * NH + h) * 16 + lane];
    float m = logit;
    #pragma unroll
    for (int o = 16; o > 0; o >>= 1) m = fmaxf(m, __shfl_xor_sync(0xffffffffu, m, o));
    float e = (lane < 16) ? __expf(logit - m) : 0.f;
    float s = e;
    #pragma unroll
    for (int o = 16; o > 0; o >>= 1) s += __shfl_xor_sync(0xffffffffu, s, o);
    const float wt = e / s;

    if (lane < 16) {
        const int LH[4] = {100, 50, 25, 13};
        const int LS[4] = {0, 10000, 12500, 13125};
        const int l = lane >> 2;
        const int w = LH[l], hh = LH[l], s0 = LS[l];
        const float lw = (float)w, lh = (float)hh;

        const float2 off = *reinterpret_cast<const float2*>(
            g_offs + (((unsigned)bq * NH + h) * 16 + lane) * 2);
        const float2 rp = *reinterpret_cast<const float2*>(refp + (unsigned)bq * 8 + l * 2);

        const float x = (rp.x + off.x / lw) * lw - 0.5f;
        const float y = (rp.y + off.y / lh) * lh - 0.5f;
        const float fx = floorf(x), fy = floorf(y);
        const float tx = x - fx, ty = y - fy;
        const int jx = (int)fx, jy = (int)fy;

        const bool xv0 = (jx >= 0) && (jx < w);
        const bool xv1 = (jx + 1 >= 0) && (jx + 1 < w);
        const bool yv0 = (jy >= 0) && (jy < hh);
        const bool yv1 = (jy + 1 >= 0) && (jy + 1 < hh);

        const int cx0 = min(max(jx, 0), w - 1);
        const int cx1 = min(max(jx + 1, 0), w - 1);
        const int cy0 = min(max(jy, 0), hh - 1);
        const int cy1 = min(max(jy + 1, 0), hh - 1);

        const float wx1 = tx, wx0 = 1.f - tx;
        const float wy1 = ty, wy0 = 1.f - ty;

        sw[h][lane][0] = (xv0 && yv0) ? wt * wx0 * wy0 : 0.f;
        sw[h][lane][1] = (xv1 && yv0) ? wt * wx1 * wy0 : 0.f;
        sw[h][lane][2] = (xv0 && yv1) ? wt * wx0 * wy1 : 0.f;
        sw[h][lane][3] = (xv1 && yv1) ? wt * wx1 * wy1 : 0.f;

        si[h][lane][0] = (s0 + cy0 * w + cx0) << 10;
        si[h][lane][1] = (s0 + cy0 * w + cx1) << 10;
        si[h][lane][2] = (s0 + cy1 * w + cx0) << 10;
        si[h][lane][3] = (s0 + cy1 * w + cx1) << 10;
    }
    __syncwarp();

    const char* __restrict__ vbc = (const char*)(
        g_value + ((unsigned)b * LEN_IN) * DM + h * HD + lane);

    float acc0 = 0.f, acc1 = 0.f;
    #pragma unroll
    for (int i = 0; i < 16; ++i) {
        const float4 wv = *reinterpret_cast<const float4*>(sw[h][i]);
        const int4   iv = *reinterpret_cast<const int4*>(si[h][i]);
        acc0 += wv.x * __ldg((const float*)(vbc + iv.x));
        acc1 += wv.y * __ldg((const float*)(vbc + iv.y));
        acc0 += wv.z * __ldg((const float*)(vbc + iv.z));
        acc1 += wv.w * __ldg((const float*)(vbc + iv.w));
    }
    sacc[tid] = acc0 + acc1;
    __syncthreads();

    // pack this row's 256 channels into bf16 hi/lo quads (same layout as prepack_A)
    if (tid < 64) {
        const int c = tid >> 2, tg = tid & 3;
        const int base = c * 16 + 2 * tg;
        AccPack[(size_t)bq * QPR + tid] =
            pack_quad(sacc[base], sacc[base + 1], sacc[base + 8], sacc[base + 9]);
    }
}

// ---------------- launch ----------------------------------------------------
extern "C" void kernel_launch(void* const* d_in, const int* in_sizes, int n_in,
                              void* d_out, int out_size)
{
    const float* query  = (const float*)d_in[0];
    const float* refp   = (const float*)d_in[1];
    const float* inputf = (const float*)d_in[2];
    const float* Wv   = (const float*)d_in[4];
    const float* bv   = (const float*)d_in[5];
    const float* Woff = (const float*)d_in[6];
    const float* boff = (const float*)d_in[7];
    const float* Wa   = (const float*)d_in[8];
    const float* ba   = (const float*)d_in[9];
    const float* Wout = (const float*)d_in[10];
    const float* bout = (const float*)d_in[11];
    float* out = (float*)d_out;

    float *valuep, *offsp, *logitsp;
    uint4 *apackp, *qpackp, *wvp, *woffp, *wap, *woutp;
    cudaGetSymbolAddress((void**)&valuep,  g_value);
    cudaGetSymbolAddress((void**)&offsp,   g_offs);
    cudaGetSymbolAddress((void**)&logitsp, g_logits);
    cudaGetSymbolAddress((void**)&apackp,  g_Apack);
    cudaGetSymbolAddress((void**)&qpackp,  g_Qpack);
    cudaGetSymbolAddress((void**)&wvp,     g_Wvp);
    cudaGetSymbolAddress((void**)&woffp,   g_Woffp);
    cudaGetSymbolAddress((void**)&wap,     g_Wap);
    cudaGetSymbolAddress((void**)&woutp,   g_Woutp);

    static bool attr_set = false;
    if (!attr_set) {
        cudaFuncSetAttribute(fused_gemm_kernel,
                             cudaFuncAttributeMaxDynamicSharedMemorySize, GSMEM_BYTES);
        attr_set = true;
    }

    // prepack
    prepack_A_dual<<<2 * MPAD * 64 / 256, 256>>>(inputf, query, apackp, qpackp);
    prepack_W_all<<<57344 / 256, 256>>>(Wv, Woff, Wa, Wout, wvp, woffp, wap, woutp);

    // fused GEMMs 1-3: value / offs / logits  (416 + 416 + 208 = 1040 tiles)
    GemmJob jv  = {apackp, wvp,   bv,   valuep,  256, 2, 416};
    GemmJob jo  = {qpackp, woffp, boff, offsp,   256, 2, 416};
    GemmJob jl  = {qpackp, wap,   ba,   logitsp, 128, 1, 208};
    fused_gemm_kernel<<<GRID_GEMM, 256, GSMEM_BYTES>>>(jv, jo, jl, 3, 1040);

    // softmax + bilinear sampling -> packed acc (writes directly into Apack)
    sample_kernel<<<BATCH * LQ, 256>>>(refp, apackp);

    // out = acc @ W_out + b_out
    GemmJob jout = {apackp, woutp, bout, out, 256, 2, 416};
    fused_gemm_kernel<<<GRID_GEMM, 256, GSMEM_BYTES>>>(jout, jout, jout, 1, 416);
}

// round 7
// speedup vs baseline: 2.4985x; 1.0501x over previous
#include <cuda_runtime.h>
#include <cuda_bf16.h>
#include <math.h>
#include <stdint.h>

#define BATCH 2
#define LQ 13294
#define LEN_IN 13294
#define DM 256
#define NH 8
#define HD 32
#define MROWS (BATCH * LQ)   // 26588
#define MPAD  26624          // 208 * 128
#define QPR   64             // packed uint4 quads per row (16 chunks * 4 tg)
#define GRID_GEMM 304        // 2 CTAs/SM * 152 SMs (GB300)

// ---------------- scratch (device globals; no allocations allowed) ----------
__device__ float g_value[(size_t)BATCH * LEN_IN * DM];   // [B, LEN_IN, NH, HD]
__device__ float g_offs[(size_t)BATCH * LQ * DM];        // [B, LQ, NH, 16, 2]
__device__ float g_logits[(size_t)BATCH * LQ * NH * 16]; // [B, LQ, NH, 16]

__device__ uint4 g_Apack[(size_t)MPAD * QPR];            // inputf pack, reused for acc
__device__ uint4 g_Qpack[(size_t)MPAD * QPR];            // query pack
__device__ uint4 g_Wvp[256 * QPR];
__device__ uint4 g_Woffp[256 * QPR];
__device__ uint4 g_Wap[128 * QPR];
__device__ uint4 g_Woutp[256 * QPR];

// ---------------- helpers ---------------------------------------------------
__device__ __forceinline__ void mma_bf16(float* d,
    unsigned a0, unsigned a1, unsigned a2, unsigned a3,
    unsigned b0, unsigned b1)
{
    asm volatile(
        "mma.sync.aligned.m16n8k16.row.col.f32.bf16.bf16.f32 "
        "{%0,%1,%2,%3}, {%4,%5,%6,%7}, {%8,%9}, {%0,%1,%2,%3};"
        : "+f"(d[0]), "+f"(d[1]), "+f"(d[2]), "+f"(d[3])
        : "r"(a0), "r"(a1), "r"(a2), "r"(a3), "r"(b0), "r"(b1));
}

__device__ __forceinline__ void cpa16(uint32_t dst, const void* src) {
    asm volatile("cp.async.ca.shared.global [%0], [%1], 16;" :: "r"(dst), "l"(src));
}
#define CPA_COMMIT() asm volatile("cp.async.commit_group;")

__device__ __forceinline__ unsigned pack_hi2(float x0, float x1,
                                             float& l0, float& l1) {
    const __nv_bfloat16 h0 = __float2bfloat16_rn(x0);
    const __nv_bfloat16 h1 = __float2bfloat16_rn(x1);
    l0 = x0 - __bfloat162float(h0);
    l1 = x1 - __bfloat162float(h1);
    __nv_bfloat162 p; p.x = h0; p.y = h1;
    return *reinterpret_cast<unsigned*>(&p);
}
__device__ __forceinline__ unsigned pack_lo2(float l0, float l1) {
    __nv_bfloat162 p;
    p.x = __float2bfloat16_rn(l0);
    p.y = __float2bfloat16_rn(l1);
    return *reinterpret_cast<unsigned*>(&p);
}
__device__ __forceinline__ uint4 pack_quad(float x0, float x1, float x2, float x3) {
    float l0, l1, l2, l3;
    uint4 q;
    q.x = pack_hi2(x0, x1, l0, l1);
    q.y = pack_hi2(x2, x3, l2, l3);
    q.z = pack_lo2(l0, l1);
    q.w = pack_lo2(l2, l3);
    return q;
}

// ---------------- prepack kernels -------------------------------------------
__global__ __launch_bounds__(256) void prepack_A_dual(
    const float* __restrict__ A0, const float* __restrict__ A1,
    uint4* __restrict__ P0, uint4* __restrict__ P1)
{
    const unsigned t = blockIdx.x * 256 + threadIdx.x;
    const unsigned HALF = (unsigned)MPAD * 64;
    const float* A = (t < HALF) ? A0 : A1;
    uint4* P = (t < HALF) ? P0 : P1;
    const unsigned lt = (t < HALF) ? t : t - HALF;
    const unsigned row = lt >> 6;
    const unsigned c = (lt >> 2) & 15, tg = lt & 3;
    float x0 = 0.f, x1 = 0.f, x2 = 0.f, x3 = 0.f;
    if (row < (unsigned)MROWS) {
        const float* a = A + (size_t)row * 256 + c * 16 + 2 * tg;
        x0 = a[0]; x1 = a[1]; x2 = a[8]; x3 = a[9];
    }
    P[lt] = pack_quad(x0, x1, x2, x3);
}

__global__ __launch_bounds__(256) void prepack_W_all(
    const float* __restrict__ Wv,  const float* __restrict__ Woff,
    const float* __restrict__ Wa,  const float* __restrict__ Wout,
    uint4* __restrict__ wvp, uint4* __restrict__ woffp,
    uint4* __restrict__ wap, uint4* __restrict__ woutp)
{
    const unsigned t = blockIdx.x * 256 + threadIdx.x;  // < 57344
    const float* B; uint4* Bp; unsigned N, lt;
    if (t < 16384)      { B = Wv;   Bp = wvp;   N = 256; lt = t; }
    else if (t < 32768) { B = Woff; Bp = woffp; N = 256; lt = t - 16384; }
    else if (t < 40960) { B = Wa;   Bp = wap;   N = 128; lt = t - 32768; }
    else                { B = Wout; Bp = woutp; N = 256; lt = t - 40960; }
    const unsigned col = lt >> 6;
    const unsigned c = (lt >> 2) & 15, tg = lt & 3;
    const unsigned k = c * 16 + 2 * tg;
    const float x0 = B[(k + 0) * N + col];
    const float x1 = B[(k + 1) * N + col];
    const float x2 = B[(k + 8) * N + col];
    const float x3 = B[(k + 9) * N + col];
    Bp[lt] = pack_quad(x0, x1, x2, x3);
}

// ---------------- tensor-core GEMM tile (3xBF16 split, prepacked) -----------
#define RQ 12
#define TILE_QUADS (128 * RQ)                 // 1536 quads = 24 KB
#define GSMEM_BYTES (4 * TILE_QUADS * 16)     // 96 KB

struct GemmJob {
    const uint4* Ap;
    const uint4* Bp;
    const float* bias;
    float* C;
    int N;       // 256 or 128
    int ncols;   // N / 128
    int ntiles;  // ncols * 208
};

__device__ __forceinline__ void gemm_tile(
    const uint4* __restrict__ Ap, const uint4* __restrict__ Bp,
    const float* __restrict__ bias, float* __restrict__ C,
    int N, int bm, int bn, uint4* smem)
{
    const int tid = threadIdx.x;
    const int lane = tid & 31;
    const int wid = tid >> 5;
    const int warp_m = wid & 1;
    const int warp_n = wid >> 1;
    const int g  = lane >> 2;
    const int tg = lane & 3;

    const int lrow0 = tid >> 3;
    const int lf    = tid & 7;

    const uint32_t smem_u32 = (uint32_t)__cvta_generic_to_shared(smem);
    const int NCH = 8;

    float acc[4][4][4];
    #pragma unroll
    for (int i = 0; i < 4; ++i)
        #pragma unroll
        for (int j = 0; j < 4; ++j)
            #pragma unroll
            for (int e = 0; e < 4; ++e) acc[i][j][e] = 0.f;

    auto load_tile = [&](int buf, int c) {
        const uint32_t abase = smem_u32 + (uint32_t)(buf * 2 * TILE_QUADS) * 16;
        const uint32_t bbase = abase + (uint32_t)TILE_QUADS * 16;
        #pragma unroll
        for (int p = 0; p < 4; ++p) {
            const int row = lrow0 + p * 32;
            cpa16(abase + (uint32_t)(row * RQ + lf) * 16,
                  Ap + (size_t)(bm + row) * QPR + c * 8 + lf);
        }
        #pragma unroll
        for (int p = 0; p < 4; ++p) {
            const int col = lrow0 + p * 32;
            cpa16(bbase + (uint32_t)(col * RQ + lf) * 16,
                  Bp + (size_t)(bn + col) * QPR + c * 8 + lf);
        }
    };

    load_tile(0, 0);
    CPA_COMMIT();

    for (int c = 0; c < NCH; ++c) {
        const int cur = c & 1;
        if (c + 1 < NCH) {
            load_tile(cur ^ 1, c + 1);
            CPA_COMMIT();
            asm volatile("cp.async.wait_group 1;");
        } else {
            asm volatile("cp.async.wait_group 0;");
        }
        __syncthreads();

        const uint4* As_ = smem + cur * 2 * TILE_QUADS;
        const uint4* Bs_ = As_ + TILE_QUADS;

        #pragma unroll
        for (int cl = 0; cl < 2; ++cl) {
            const int qoff = cl * 4 + tg;
            uint4 bf[4];
            #pragma unroll
            for (int ni = 0; ni < 4; ++ni)
                bf[ni] = Bs_[(warp_n * 32 + ni * 8 + g) * RQ + qoff];

            #pragma unroll
            for (int mi = 0; mi < 4; ++mi) {
                const uint4 a0 = As_[(warp_m * 64 + mi * 16 + g) * RQ + qoff];
                const uint4 a1 = As_[(warp_m * 64 + mi * 16 + g + 8) * RQ + qoff];
                #pragma unroll
                for (int ni = 0; ni < 4; ++ni) {
                    mma_bf16(acc[mi][ni], a0.x, a1.x, a0.y, a1.y, bf[ni].x, bf[ni].y);
                    mma_bf16(acc[mi][ni], a0.x, a1.x, a0.y, a1.y, bf[ni].z, bf[ni].w);
                    mma_bf16(acc[mi][ni], a0.z, a1.z, a0.w, a1.w, bf[ni].x, bf[ni].y);
                }
            }
        }
        __syncthreads();
    }

    #pragma unroll
    for (int mi = 0; mi < 4; ++mi) {
        const int row0 = bm + warp_m * 64 + mi * 16 + g;
        const int row1 = row0 + 8;
        #pragma unroll
        for (int ni = 0; ni < 4; ++ni) {
            const int col = bn + warp_n * 32 + ni * 8 + 2 * tg;
            const float bx = bias[col], by = bias[col + 1];
            if (row0 < MROWS) {
                float2 v = {acc[mi][ni][0] + bx, acc[mi][ni][1] + by};
                *reinterpret_cast<float2*>(C + (size_t)row0 * N + col) = v;
            }
            if (row1 < MROWS) {
                float2 v = {acc[mi][ni][2] + bx, acc[mi][ni][3] + by};
                *reinterpret_cast<float2*>(C + (size_t)row1 * N + col) = v;
            }
        }
    }
}

__global__ __launch_bounds__(256, 2) void fused_gemm_kernel(
    GemmJob j0, GemmJob j1, GemmJob j2, int njobs, int total)
{
    extern __shared__ uint4 smem[];
    for (int t = blockIdx.x; t < total; t += gridDim.x) {
        GemmJob jb = j0;
        int lt = t;
        if (njobs > 1 && lt >= jb.ntiles) {
            lt -= jb.ntiles; jb = j1;
            if (njobs > 2 && lt >= jb.ntiles) { lt -= jb.ntiles; jb = j2; }
        }
        int bm, bn;
        if (jb.ncols == 2) { bm = (lt >> 1) * 128; bn = (lt & 1) * 128; }
        else               { bm = lt * 128;        bn = 0; }
        gemm_tile(jb.Ap, jb.Bp, jb.bias, jb.C, jb.N, bm, bn, smem);
    }
}

// ---------------- sampling + softmax + fused bf16 hi/lo packing -------------
// One block per (b,q); one warp per head.
// Setup (lanes 0..15): softmax + bilinear weights/indices -> comb[h][p][4] int2.
// Gather: lane = {sub=corner 0..3} x {cl=channel-quad 0..7}; per point one
// LDS.64 + one LDG.128 + 4 FFMA. Cross-corner reduce via 8 shuffles at end.
__global__ __launch_bounds__(256) void sample_kernel(
    const float* __restrict__ refp, uint4* __restrict__ AccPack)
{
    __shared__ __align__(16) int2  comb[NH][16][4];  // {byte offset, weight bits}
    __shared__ __align__(16) float sacc[256];

    const int bq = blockIdx.x;
    const int b  = (bq >= LQ) ? 1 : 0;
    const int tid = threadIdx.x;
    const int h  = tid >> 5;
    const int lane = tid & 31;

    // ---- softmax over the 16 logits ----
    float logit = -INFINITY;
    if (lane < 16) logit = g_logits[((unsigned)bq * NH + h) * 16 + lane];
    float m = logit;
    #pragma unroll
    for (int o = 16; o > 0; o >>= 1) m = fmaxf(m, __shfl_xor_sync(0xffffffffu, m, o));
    float e = (lane < 16) ? __expf(logit - m) : 0.f;
    float s = e;
    #pragma unroll
    for (int o = 16; o > 0; o >>= 1) s += __shfl_xor_sync(0xffffffffu, s, o);
    const float wt = e / s;

    if (lane < 16) {
        const int LH[4] = {100, 50, 25, 13};
        const int LS[4] = {0, 10000, 12500, 13125};
        const int l = lane >> 2;
        const int w = LH[l], hh = LH[l], s0 = LS[l];
        const float lw = (float)w, lh = (float)hh;

        const float2 off = *reinterpret_cast<const float2*>(
            g_offs + (((unsigned)bq * NH + h) * 16 + lane) * 2);
        const float2 rp = *reinterpret_cast<const float2*>(refp + (unsigned)bq * 8 + l * 2);

        const float x = (rp.x + off.x / lw) * lw - 0.5f;
        const float y = (rp.y + off.y / lh) * lh - 0.5f;
        const float fx = floorf(x), fy = floorf(y);
        const float tx = x - fx, ty = y - fy;
        const int jx = (int)fx, jy = (int)fy;

        const bool xv0 = (jx >= 0) && (jx < w);
        const bool xv1 = (jx + 1 >= 0) && (jx + 1 < w);
        const bool yv0 = (jy >= 0) && (jy < hh);
        const bool yv1 = (jy + 1 >= 0) && (jy + 1 < hh);

        const int cx0 = min(max(jx, 0), w - 1);
        const int cx1 = min(max(jx + 1, 0), w - 1);
        const int cy0 = min(max(jy, 0), hh - 1);
        const int cy1 = min(max(jy + 1, 0), hh - 1);

        const float wx1 = tx, wx0 = 1.f - tx;
        const float wy1 = ty, wy0 = 1.f - ty;

        const float w0 = (xv0 && yv0) ? wt * wx0 * wy0 : 0.f;
        const float w1 = (xv1 && yv0) ? wt * wx1 * wy0 : 0.f;
        const float w2 = (xv0 && yv1) ? wt * wx0 * wy1 : 0.f;
        const float w3 = (xv1 && yv1) ? wt * wx1 * wy1 : 0.f;

        comb[h][lane][0] = make_int2((s0 + cy0 * w + cx0) << 10, __float_as_int(w0));
        comb[h][lane][1] = make_int2((s0 + cy0 * w + cx1) << 10, __float_as_int(w1));
        comb[h][lane][2] = make_int2((s0 + cy1 * w + cx0) << 10, __float_as_int(w2));
        comb[h][lane][3] = make_int2((s0 + cy1 * w + cx1) << 10, __float_as_int(w3));
    }
    __syncwarp();

    // ---- vectorized gather: sub = corner, cl = channel quad ----
    const int sub = lane >> 3;
    const int cl  = lane & 7;
    const char* __restrict__ base = (const char*)(
        g_value + ((unsigned)b * LEN_IN) * DM + h * HD + cl * 4);

    float4 acc = {0.f, 0.f, 0.f, 0.f};
    #pragma unroll
    for (int p = 0; p < 16; ++p) {
        const int2 cw = comb[h][p][sub];
        const float4 v = __ldg(reinterpret_cast<const float4*>(base + cw.x));
        const float w = __int_as_float(cw.y);
        acc.x += w * v.x;
        acc.y += w * v.y;
        acc.z += w * v.z;
        acc.w += w * v.w;
    }

    // reduce over the 4 corners (lanes cl, cl+8, cl+16, cl+24)
    #pragma unroll
    for (int o = 8; o <= 16; o <<= 1) {
        acc.x += __shfl_xor_sync(0xffffffffu, acc.x, o);
        acc.y += __shfl_xor_sync(0xffffffffu, acc.y, o);
        acc.z += __shfl_xor_sync(0xffffffffu, acc.z, o);
        acc.w += __shfl_xor_sync(0xffffffffu, acc.w, o);
    }
    if (sub == 0)
        *reinterpret_cast<float4*>(&sacc[h * HD + cl * 4]) = acc;
    __syncthreads();

    // pack this row's 256 channels into bf16 hi/lo quads (prepack_A layout)
    if (tid < 64) {
        const int c = tid >> 2, tg = tid & 3;
        const int bbase = c * 16 + 2 * tg;
        AccPack[(size_t)bq * QPR + tid] =
            pack_quad(sacc[bbase], sacc[bbase + 1], sacc[bbase + 8], sacc[bbase + 9]);
    }
}

// ---------------- launch ----------------------------------------------------
extern "C" void kernel_launch(void* const* d_in, const int* in_sizes, int n_in,
                              void* d_out, int out_size)
{
    const float* query  = (const float*)d_in[0];
    const float* refp   = (const float*)d_in[1];
    const float* inputf = (const float*)d_in[2];
    const float* Wv   = (const float*)d_in[4];
    const float* bv   = (const float*)d_in[5];
    const float* Woff = (const float*)d_in[6];
    const float* boff = (const float*)d_in[7];
    const float* Wa   = (const float*)d_in[8];
    const float* ba   = (const float*)d_in[9];
    const float* Wout = (const float*)d_in[10];
    const float* bout = (const float*)d_in[11];
    float* out = (float*)d_out;

    float *valuep, *offsp, *logitsp;
    uint4 *apackp, *qpackp, *wvp, *woffp, *wap, *woutp;
    cudaGetSymbolAddress((void**)&valuep,  g_value);
    cudaGetSymbolAddress((void**)&offsp,   g_offs);
    cudaGetSymbolAddress((void**)&logitsp, g_logits);
    cudaGetSymbolAddress((void**)&apackp,  g_Apack);
    cudaGetSymbolAddress((void**)&qpackp,  g_Qpack);
    cudaGetSymbolAddress((void**)&wvp,     g_Wvp);
    cudaGetSymbolAddress((void**)&woffp,   g_Woffp);
    cudaGetSymbolAddress((void**)&wap,     g_Wap);
    cudaGetSymbolAddress((void**)&woutp,   g_Woutp);

    static bool attr_set = false;
    if (!attr_set) {
        cudaFuncSetAttribute(fused_gemm_kernel,
                             cudaFuncAttributeMaxDynamicSharedMemorySize, GSMEM_BYTES);
        attr_set = true;
    }

    // prepack
    prepack_A_dual<<<2 * MPAD * 64 / 256, 256>>>(inputf, query, apackp, qpackp);
    prepack_W_all<<<57344 / 256, 256>>>(Wv, Woff, Wa, Wout, wvp, woffp, wap, woutp);

    // fused GEMMs 1-3: value / offs / logits  (416 + 416 + 208 = 1040 tiles)
    GemmJob jv  = {apackp, wvp,   bv,   valuep,  256, 2, 416};
    GemmJob jo  = {qpackp, woffp, boff, offsp,   256, 2, 416};
    GemmJob jl  = {qpackp, wap,   ba,   logitsp, 128, 1, 208};
    fused_gemm_kernel<<<GRID_GEMM, 256, GSMEM_BYTES>>>(jv, jo, jl, 3, 1040);

    // softmax + bilinear sampling -> packed acc (writes directly into Apack)
    sample_kernel<<<BATCH * LQ, 256>>>(refp, apackp);

    // out = acc @ W_out + b_out
    GemmJob jout = {apackp, woutp, bout, out, 256, 2, 416};
    fused_gemm_kernel<<<GRID_GEMM, 256, GSMEM_BYTES>>>(jout, jout, jout, 1, 416);
}

// round 8
// speedup vs baseline: 2.6419x; 1.0574x over previous
#include <cuda_runtime.h>
#include <cuda_bf16.h>
#include <math.h>
#include <stdint.h>

#define BATCH 2
#define LQ 13294
#define LEN_IN 13294
#define DM 256
#define NH 8
#define HD 32
#define MROWS (BATCH * LQ)   // 26588
#define MPAD  26624          // 208 * 128
#define QPR   64             // packed uint4 quads per row (16 chunks * 4 tg)
#define GRID_GEMM 304        // 2 CTAs/SM * 152 SMs (GB300)

// ---------------- scratch (device globals; no allocations allowed) ----------
__device__ float g_value[(size_t)BATCH * LEN_IN * DM];   // [B, LEN_IN, NH, HD]
__device__ float g_offs[(size_t)BATCH * LQ * DM];        // [B, LQ, NH, 16, 2]
__device__ float g_logits[(size_t)BATCH * LQ * NH * 16]; // [B, LQ, NH, 16]

__device__ uint4 g_Apack[(size_t)MPAD * QPR];            // inputf pack, reused for acc
__device__ uint4 g_Qpack[(size_t)MPAD * QPR];            // query pack
__device__ uint4 g_Wvp[256 * QPR];
__device__ uint4 g_Woffp[256 * QPR];
__device__ uint4 g_Wap[128 * QPR];
__device__ uint4 g_Woutp[256 * QPR];

// ---------------- helpers ---------------------------------------------------
__device__ __forceinline__ void mma_bf16(float* d,
    unsigned a0, unsigned a1, unsigned a2, unsigned a3,
    unsigned b0, unsigned b1)
{
    asm volatile(
        "mma.sync.aligned.m16n8k16.row.col.f32.bf16.bf16.f32 "
        "{%0,%1,%2,%3}, {%4,%5,%6,%7}, {%8,%9}, {%0,%1,%2,%3};"
        : "+f"(d[0]), "+f"(d[1]), "+f"(d[2]), "+f"(d[3])
        : "r"(a0), "r"(a1), "r"(a2), "r"(a3), "r"(b0), "r"(b1));
}

__device__ __forceinline__ void cpa16(uint32_t dst, const void* src) {
    asm volatile("cp.async.ca.shared.global [%0], [%1], 16;" :: "r"(dst), "l"(src));
}
#define CPA_COMMIT() asm volatile("cp.async.commit_group;")

__device__ __forceinline__ unsigned pack_hi2(float x0, float x1,
                                             float& l0, float& l1) {
    const __nv_bfloat16 h0 = __float2bfloat16_rn(x0);
    const __nv_bfloat16 h1 = __float2bfloat16_rn(x1);
    l0 = x0 - __bfloat162float(h0);
    l1 = x1 - __bfloat162float(h1);
    __nv_bfloat162 p; p.x = h0; p.y = h1;
    return *reinterpret_cast<unsigned*>(&p);
}
__device__ __forceinline__ unsigned pack_lo2(float l0, float l1) {
    __nv_bfloat162 p;
    p.x = __float2bfloat16_rn(l0);
    p.y = __float2bfloat16_rn(l1);
    return *reinterpret_cast<unsigned*>(&p);
}
__device__ __forceinline__ uint4 pack_quad(float x0, float x1, float x2, float x3) {
    float l0, l1, l2, l3;
    uint4 q;
    q.x = pack_hi2(x0, x1, l0, l1);
    q.y = pack_hi2(x2, x3, l2, l3);
    q.z = pack_lo2(l0, l1);
    q.w = pack_lo2(l2, l3);
    return q;
}

// ---------------- fused prepack (A0, A1, all weights in one launch) ----------
#define APART (2u * MPAD * 64u)
__global__ __launch_bounds__(256) void prepack_all(
    const float* __restrict__ A0, const float* __restrict__ A1,
    uint4* __restrict__ P0, uint4* __restrict__ P1,
    const float* __restrict__ Wv,  const float* __restrict__ Woff,
    const float* __restrict__ Wa,  const float* __restrict__ Wout,
    uint4* __restrict__ wvp, uint4* __restrict__ woffp,
    uint4* __restrict__ wap, uint4* __restrict__ woutp)
{
    const unsigned t = blockIdx.x * 256 + threadIdx.x;
    if (t < APART) {
        const unsigned HALF = (unsigned)MPAD * 64;
        const float* A = (t < HALF) ? A0 : A1;
        uint4* P = (t < HALF) ? P0 : P1;
        const unsigned lt = (t < HALF) ? t : t - HALF;
        const unsigned row = lt >> 6;
        const unsigned c = (lt >> 2) & 15, tg = lt & 3;
        float x0 = 0.f, x1 = 0.f, x2 = 0.f, x3 = 0.f;
        if (row < (unsigned)MROWS) {
            const float* a = A + (size_t)row * 256 + c * 16 + 2 * tg;
            x0 = a[0]; x1 = a[1]; x2 = a[8]; x3 = a[9];
        }
        P[lt] = pack_quad(x0, x1, x2, x3);
    } else {
        const unsigned u = t - APART;   // < 57344
        const float* B; uint4* Bp; unsigned N, lt;
        if (u < 16384)      { B = Wv;   Bp = wvp;   N = 256; lt = u; }
        else if (u < 32768) { B = Woff; Bp = woffp; N = 256; lt = u - 16384; }
        else if (u < 40960) { B = Wa;   Bp = wap;   N = 128; lt = u - 32768; }
        else                { B = Wout; Bp = woutp; N = 256; lt = u - 40960; }
        const unsigned col = lt >> 6;
        const unsigned c = (lt >> 2) & 15, tg = lt & 3;
        const unsigned k = c * 16 + 2 * tg;
        const float x0 = B[(k + 0) * N + col];
        const float x1 = B[(k + 1) * N + col];
        const float x2 = B[(k + 8) * N + col];
        const float x3 = B[(k + 9) * N + col];
        Bp[lt] = pack_quad(x0, x1, x2, x3);
    }
}

// ---------------- tensor-core GEMM tile (3xBF16 split, prepacked) -----------
#define RQ 12
#define TILE_QUADS (128 * RQ)                 // 1536 quads = 24 KB
#define GSMEM_BYTES (4 * TILE_QUADS * 16)     // 96 KB

struct GemmJob {
    const uint4* Ap;
    const uint4* Bp;
    const float* bias;
    float* C;
    int N;       // 256 or 128
    int ncols;   // N / 128
    int ntiles;  // ncols * 208
};

__device__ __forceinline__ void gemm_tile(
    const uint4* __restrict__ Ap, const uint4* __restrict__ Bp,
    const float* __restrict__ bias, float* __restrict__ C,
    int N, int bm, int bn, uint4* smem)
{
    const int tid = threadIdx.x;
    const int lane = tid & 31;
    const int wid = tid >> 5;
    const int warp_m = wid & 1;
    const int warp_n = wid >> 1;
    const int g  = lane >> 2;
    const int tg = lane & 3;

    const int lrow0 = tid >> 3;
    const int lf    = tid & 7;

    const uint32_t smem_u32 = (uint32_t)__cvta_generic_to_shared(smem);
    const int NCH = 8;

    float acc[4][4][4];
    #pragma unroll
    for (int i = 0; i < 4; ++i)
        #pragma unroll
        for (int j = 0; j < 4; ++j)
            #pragma unroll
            for (int e = 0; e < 4; ++e) acc[i][j][e] = 0.f;

    auto load_tile = [&](int buf, int c) {
        const uint32_t abase = smem_u32 + (uint32_t)(buf * 2 * TILE_QUADS) * 16;
        const uint32_t bbase = abase + (uint32_t)TILE_QUADS * 16;
        #pragma unroll
        for (int p = 0; p < 4; ++p) {
            const int row = lrow0 + p * 32;
            cpa16(abase + (uint32_t)(row * RQ + lf) * 16,
                  Ap + (size_t)(bm + row) * QPR + c * 8 + lf);
        }
        #pragma unroll
        for (int p = 0; p < 4; ++p) {
            const int col = lrow0 + p * 32;
            cpa16(bbase + (uint32_t)(col * RQ + lf) * 16,
                  Bp + (size_t)(bn + col) * QPR + c * 8 + lf);
        }
    };

    load_tile(0, 0);
    CPA_COMMIT();

    for (int c = 0; c < NCH; ++c) {
        const int cur = c & 1;
        if (c + 1 < NCH) {
            load_tile(cur ^ 1, c + 1);
            CPA_COMMIT();
            asm volatile("cp.async.wait_group 1;");
        } else {
            asm volatile("cp.async.wait_group 0;");
        }
        __syncthreads();

        const uint4* As_ = smem + cur * 2 * TILE_QUADS;
        const uint4* Bs_ = As_ + TILE_QUADS;

        #pragma unroll
        for (int cl = 0; cl < 2; ++cl) {
            const int qoff = cl * 4 + tg;
            uint4 bf[4];
            #pragma unroll
            for (int ni = 0; ni < 4; ++ni)
                bf[ni] = Bs_[(warp_n * 32 + ni * 8 + g) * RQ + qoff];

            #pragma unroll
            for (int mi = 0; mi < 4; ++mi) {
                const uint4 a0 = As_[(warp_m * 64 + mi * 16 + g) * RQ + qoff];
                const uint4 a1 = As_[(warp_m * 64 + mi * 16 + g + 8) * RQ + qoff];
                #pragma unroll
                for (int ni = 0; ni < 4; ++ni) {
                    mma_bf16(acc[mi][ni], a0.x, a1.x, a0.y, a1.y, bf[ni].x, bf[ni].y);
                    mma_bf16(acc[mi][ni], a0.x, a1.x, a0.y, a1.y, bf[ni].z, bf[ni].w);
                    mma_bf16(acc[mi][ni], a0.z, a1.z, a0.w, a1.w, bf[ni].x, bf[ni].y);
                }
            }
        }
        __syncthreads();
    }

    #pragma unroll
    for (int mi = 0; mi < 4; ++mi) {
        const int row0 = bm + warp_m * 64 + mi * 16 + g;
        const int row1 = row0 + 8;
        #pragma unroll
        for (int ni = 0; ni < 4; ++ni) {
            const int col = bn + warp_n * 32 + ni * 8 + 2 * tg;
            const float bx = bias[col], by = bias[col + 1];
            if (row0 < MROWS) {
                float2 v = {acc[mi][ni][0] + bx, acc[mi][ni][1] + by};
                *reinterpret_cast<float2*>(C + (size_t)row0 * N + col) = v;
            }
            if (row1 < MROWS) {
                float2 v = {acc[mi][ni][2] + bx, acc[mi][ni][3] + by};
                *reinterpret_cast<float2*>(C + (size_t)row1 * N + col) = v;
            }
        }
    }
}

__global__ __launch_bounds__(256, 2) void fused_gemm_kernel(
    GemmJob j0, GemmJob j1, GemmJob j2, int njobs, int total)
{
    extern __shared__ uint4 smem[];
    for (int t = blockIdx.x; t < total; t += gridDim.x) {
        GemmJob jb = j0;
        int lt = t;
        if (njobs > 1 && lt >= jb.ntiles) {
            lt -= jb.ntiles; jb = j1;
            if (njobs > 2 && lt >= jb.ntiles) { lt -= jb.ntiles; jb = j2; }
        }
        int bm, bn;
        if (jb.ncols == 2) { bm = (lt >> 1) * 128; bn = (lt & 1) * 128; }
        else               { bm = lt * 128;        bn = 0; }
        gemm_tile(jb.Ap, jb.Bp, jb.bias, jb.C, jb.N, bm, bn, smem);
    }
}

// ---------------- sampling + softmax + fused bf16 hi/lo packing -------------
// One block per (b,q); warps fully independent (one warp per head, no
// __syncthreads). Gather: sub = corner, cl = channel quad; per point one
// LDS.64 + one LDG.128 + 4 FFMA. Levels 0-1 use __ldcg (L2-only, no L1
// pollution); levels 2-3 use __ldg (small, L1-resident). Cross-corner
// reduce by shuffles; per-warp smem patch redistributes channels for the
// bf16 hi/lo pack (warp packs its own head's 8 quads).
__global__ __launch_bounds__(256) void sample_kernel(
    const float* __restrict__ refp, uint4* __restrict__ AccPack)
{
    __shared__ __align__(16) int2  comb[NH][16][4];  // {byte offset, weight bits}
    __shared__ __align__(16) float swacc[NH][32];    // per-warp channel patch

    const int bq = blockIdx.x;
    const int b  = (bq >= LQ) ? 1 : 0;
    const int tid = threadIdx.x;
    const int h  = tid >> 5;
    const int lane = tid & 31;

    // ---- softmax over the 16 logits ----
    float logit = -INFINITY;
    if (lane < 16) logit = g_logits[((unsigned)bq * NH + h) * 16 + lane];
    float m = logit;
    #pragma unroll
    for (int o = 16; o > 0; o >>= 1) m = fmaxf(m, __shfl_xor_sync(0xffffffffu, m, o));
    float e = (lane < 16) ? __expf(logit - m) : 0.f;
    float s = e;
    #pragma unroll
    for (int o = 16; o > 0; o >>= 1) s += __shfl_xor_sync(0xffffffffu, s, o);
    const float wt = e / s;

    if (lane < 16) {
        const int LH[4] = {100, 50, 25, 13};
        const int LS[4] = {0, 10000, 12500, 13125};
        const int l = lane >> 2;
        const int w = LH[l], hh = LH[l], s0 = LS[l];
        const float lw = (float)w, lh = (float)hh;

        const float2 off = *reinterpret_cast<const float2*>(
            g_offs + (((unsigned)bq * NH + h) * 16 + lane) * 2);
        const float2 rp = *reinterpret_cast<const float2*>(refp + (unsigned)bq * 8 + l * 2);

        const float x = (rp.x + off.x / lw) * lw - 0.5f;
        const float y = (rp.y + off.y / lh) * lh - 0.5f;
        const float fx = floorf(x), fy = floorf(y);
        const float tx = x - fx, ty = y - fy;
        const int jx = (int)fx, jy = (int)fy;

        const bool xv0 = (jx >= 0) && (jx < w);
        const bool xv1 = (jx + 1 >= 0) && (jx + 1 < w);
        const bool yv0 = (jy >= 0) && (jy < hh);
        const bool yv1 = (jy + 1 >= 0) && (jy + 1 < hh);

        const int cx0 = min(max(jx, 0), w - 1);
        const int cx1 = min(max(jx + 1, 0), w - 1);
        const int cy0 = min(max(jy, 0), hh - 1);
        const int cy1 = min(max(jy + 1, 0), hh - 1);

        const float wx1 = tx, wx0 = 1.f - tx;
        const float wy1 = ty, wy0 = 1.f - ty;

        const float w0 = (xv0 && yv0) ? wt * wx0 * wy0 : 0.f;
        const float w1 = (xv1 && yv0) ? wt * wx1 * wy0 : 0.f;
        const float w2 = (xv0 && yv1) ? wt * wx0 * wy1 : 0.f;
        const float w3 = (xv1 && yv1) ? wt * wx1 * wy1 : 0.f;

        comb[h][lane][0] = make_int2((s0 + cy0 * w + cx0) << 10, __float_as_int(w0));
        comb[h][lane][1] = make_int2((s0 + cy0 * w + cx1) << 10, __float_as_int(w1));
        comb[h][lane][2] = make_int2((s0 + cy1 * w + cx0) << 10, __float_as_int(w2));
        comb[h][lane][3] = make_int2((s0 + cy1 * w + cx1) << 10, __float_as_int(w3));
    }
    __syncwarp();

    // ---- vectorized gather ----
    const int sub = lane >> 3;
    const int cl  = lane & 7;
    const char* __restrict__ base = (const char*)(
        g_value + ((unsigned)b * LEN_IN) * DM + h * HD + cl * 4);

    float4 acc = {0.f, 0.f, 0.f, 0.f};
    #pragma unroll
    for (int p = 0; p < 16; ++p) {
        const int2 cw = comb[h][p][sub];
        float4 v;
        if (p < 8)   // levels 0-1: streaming, keep out of L1
            v = __ldcg(reinterpret_cast<const float4*>(base + cw.x));
        else          // levels 2-3: small working set, L1-resident
            v = __ldg(reinterpret_cast<const float4*>(base + cw.x));
        const float w = __int_as_float(cw.y);
        acc.x += w * v.x;
        acc.y += w * v.y;
        acc.z += w * v.z;
        acc.w += w * v.w;
    }

    // reduce over the 4 corners (lanes cl, cl+8, cl+16, cl+24)
    #pragma unroll
    for (int o = 8; o <= 16; o <<= 1) {
        acc.x += __shfl_xor_sync(0xffffffffu, acc.x, o);
        acc.y += __shfl_xor_sync(0xffffffffu, acc.y, o);
        acc.z += __shfl_xor_sync(0xffffffffu, acc.z, o);
        acc.w += __shfl_xor_sync(0xffffffffu, acc.w, o);
    }
    if (sub == 0)
        *reinterpret_cast<float4*>(&swacc[h][cl * 4]) = acc;
    __syncwarp();

    // ---- pack this head's 32 channels into 8 bf16 hi/lo quads ----
    if (lane < 8) {
        const int cloc = lane >> 2, tg = lane & 3;     // quad within head
        const int bs = cloc * 16 + 2 * tg;             // local channel base
        AccPack[(size_t)bq * QPR + h * 8 + cloc * 4 + tg] =
            pack_quad(swacc[h][bs], swacc[h][bs + 1],
                      swacc[h][bs + 8], swacc[h][bs + 9]);
    }
}

// ---------------- launch ----------------------------------------------------
extern "C" void kernel_launch(void* const* d_in, const int* in_sizes, int n_in,
                              void* d_out, int out_size)
{
    const float* query  = (const float*)d_in[0];
    const float* refp   = (const float*)d_in[1];
    const float* inputf = (const float*)d_in[2];
    const float* Wv   = (const float*)d_in[4];
    const float* bv   = (const float*)d_in[5];
    const float* Woff = (const float*)d_in[6];
    const float* boff = (const float*)d_in[7];
    const float* Wa   = (const float*)d_in[8];
    const float* ba   = (const float*)d_in[9];
    const float* Wout = (const float*)d_in[10];
    const float* bout = (const float*)d_in[11];
    float* out = (float*)d_out;

    float *valuep, *offsp, *logitsp;
    uint4 *apackp, *qpackp, *wvp, *woffp, *wap, *woutp;
    cudaGetSymbolAddress((void**)&valuep,  g_value);
    cudaGetSymbolAddress((void**)&offsp,   g_offs);
    cudaGetSymbolAddress((void**)&logitsp, g_logits);
    cudaGetSymbolAddress((void**)&apackp,  g_Apack);
    cudaGetSymbolAddress((void**)&qpackp,  g_Qpack);
    cudaGetSymbolAddress((void**)&wvp,     g_Wvp);
    cudaGetSymbolAddress((void**)&woffp,   g_Woffp);
    cudaGetSymbolAddress((void**)&wap,     g_Wap);
    cudaGetSymbolAddress((void**)&woutp,   g_Woutp);

    static bool attr_set = false;
    if (!attr_set) {
        cudaFuncSetAttribute(fused_gemm_kernel,
                             cudaFuncAttributeMaxDynamicSharedMemorySize, GSMEM_BYTES);
        attr_set = true;
    }

    // fused prepack: A0, A1, all weights
    const unsigned npre = APART + 57344u;
    prepack_all<<<(npre + 255) / 256, 256>>>(
        inputf, query, apackp, qpackp,
        Wv, Woff, Wa, Wout, wvp, woffp, wap, woutp);

    // fused GEMMs 1-3: value / offs / logits  (416 + 416 + 208 = 1040 tiles)
    GemmJob jv  = {apackp, wvp,   bv,   valuep,  256, 2, 416};
    GemmJob jo  = {qpackp, woffp, boff, offsp,   256, 2, 416};
    GemmJob jl  = {qpackp, wap,   ba,   logitsp, 128, 1, 208};
    fused_gemm_kernel<<<GRID_GEMM, 256, GSMEM_BYTES>>>(jv, jo, jl, 3, 1040);

    // softmax + bilinear sampling -> packed acc (writes directly into Apack)
    sample_kernel<<<BATCH * LQ, 256>>>(refp, apackp);

    // out = acc @ W_out + b_out
    GemmJob jout = {apackp, woutp, bout, out, 256, 2, 416};
    fused_gemm_kernel<<<GRID_GEMM, 256, GSMEM_BYTES>>>(jout, jout, jout, 1, 416);
}